// round 2
// baseline (speedup 1.0000x reference)
#include <cuda_runtime.h>
#include <cstdint>

#define LN_EPS 1e-5f
#define SENT 0x007FFFFFu   // order-encoded -inf

// ---------------- scratch (device globals: allocation-free) ----------------
__device__ float    g_bufA[100000 * 512];   // layer0 out (stride 128) / layer2 out (stride 512)
__device__ float    g_bufB[100000 * 256];   // layer1 out (stride 256)
__device__ float    g_hmid[100000 * 64];    // LN+ReLU intermediate
__device__ unsigned g_pool[10000 * 512];    // encoded cluster-max
__device__ float    g_colsq[512];           // column sum of squares

// ---------------- order-preserving float <-> uint -------------------------
__device__ __forceinline__ unsigned ordf(float f) {
    unsigned u = __float_as_uint(f);
    return (u & 0x80000000u) ? ~u : (u | 0x80000000u);
}
__device__ __forceinline__ float unordf(unsigned e) {
    return __uint_as_float((e & 0x80000000u) ? (e ^ 0x80000000u) : ~e);
}

// ---------------- GEMM1 + bias + LayerNorm + ReLU --------------------------
// h_mid[N,64] = relu(LN(x[N,CIN] @ W1[CIN,64] + b1) * g + be)
template<int CIN>
__global__ __launch_bounds__(256) void mlp1_kernel(
    const float* __restrict__ x, const float* __restrict__ W1,
    const float* __restrict__ b1, const float* __restrict__ gam,
    const float* __restrict__ bet, float* __restrict__ hmid, int n)
{
    __shared__ __align__(16) float As[16][68];
    __shared__ __align__(16) float Ws[16][68];
    const int t  = threadIdx.x;
    const int tx = t & 15, ty = t >> 4;
    const int row0 = blockIdx.x * 64;
    const int lm = t >> 4, lk = t & 15;
    const int wj = t & 63, wk = t >> 6;

    float acc[4][4] = {};

    for (int k0 = 0; k0 < CIN; k0 += 16) {
#pragma unroll
        for (int i = 0; i < 4; i++) {
            int m = lm + i * 16;
            int r = row0 + m;
            As[lk][m] = (r < n) ? x[(size_t)r * CIN + k0 + lk] : 0.f;
        }
#pragma unroll
        for (int i = 0; i < 4; i++) {
            int k = wk + i * 4;
            Ws[k][wj] = W1[(size_t)(k0 + k) * 64 + wj];
        }
        __syncthreads();
#pragma unroll
        for (int kk = 0; kk < 16; kk++) {
            float4 a = *(const float4*)&As[kk][ty * 4];
            float4 b = *(const float4*)&Ws[kk][tx * 4];
            acc[0][0] += a.x * b.x; acc[0][1] += a.x * b.y; acc[0][2] += a.x * b.z; acc[0][3] += a.x * b.w;
            acc[1][0] += a.y * b.x; acc[1][1] += a.y * b.y; acc[1][2] += a.y * b.z; acc[1][3] += a.y * b.w;
            acc[2][0] += a.z * b.x; acc[2][1] += a.z * b.y; acc[2][2] += a.z * b.z; acc[2][3] += a.z * b.w;
            acc[3][0] += a.w * b.x; acc[3][1] += a.w * b.y; acc[3][2] += a.w * b.z; acc[3][3] += a.w * b.w;
        }
        __syncthreads();
    }

    const float4 b1v = *(const float4*)(b1  + tx * 4);
    const float4 gv  = *(const float4*)(gam + tx * 4);
    const float4 bev = *(const float4*)(bet + tx * 4);

#pragma unroll
    for (int mi = 0; mi < 4; mi++) {
        float v0 = acc[mi][0] + b1v.x, v1 = acc[mi][1] + b1v.y;
        float v2 = acc[mi][2] + b1v.z, v3 = acc[mi][3] + b1v.w;
        float s = v0 + v1 + v2 + v3;
        float q = v0 * v0 + v1 * v1 + v2 * v2 + v3 * v3;
#pragma unroll
        for (int off = 1; off < 16; off <<= 1) {
            s += __shfl_xor_sync(0xffffffffu, s, off);
            q += __shfl_xor_sync(0xffffffffu, q, off);
        }
        float mu  = s * (1.0f / 64.0f);
        float var = q * (1.0f / 64.0f) - mu * mu;
        float rs  = rsqrtf(var + LN_EPS);
        v0 = fmaxf((v0 - mu) * rs * gv.x + bev.x, 0.f);
        v1 = fmaxf((v1 - mu) * rs * gv.y + bev.y, 0.f);
        v2 = fmaxf((v2 - mu) * rs * gv.z + bev.z, 0.f);
        v3 = fmaxf((v3 - mu) * rs * gv.w + bev.w, 0.f);
        int r = row0 + ty * 4 + mi;
        if (r < n)
            *(float4*)&hmid[(size_t)r * 64 + tx * 4] = make_float4(v0, v1, v2, v3);
    }
}

// ---------------- GEMM2 + bias, and seed agg-half with sentinel ------------
// y[:, 0:COUT] = hmid @ W2[64,COUT] + b2 ; yu[:, COUT:2*COUT] = SENT
template<int COUT>
__global__ __launch_bounds__(256) void mlp2_kernel(
    const float* __restrict__ hmid, const float* __restrict__ W2,
    const float* __restrict__ b2, float* __restrict__ y,
    unsigned* __restrict__ yu, int n)
{
    __shared__ __align__(16) float As[16][68];
    __shared__ __align__(16) float Ws[16][68];
    const int t  = threadIdx.x;
    const int tx = t & 15, ty = t >> 4;
    const int row0 = blockIdx.x * 64;
    const int j0   = blockIdx.y * 64;
    const int S = 2 * COUT;
    const int lm = t >> 4, lk = t & 15;
    const int wj = t & 63, wk = t >> 6;

    float acc[4][4] = {};

#pragma unroll
    for (int k0 = 0; k0 < 64; k0 += 16) {
#pragma unroll
        for (int i = 0; i < 4; i++) {
            int m = lm + i * 16;
            int r = row0 + m;
            As[lk][m] = (r < n) ? hmid[(size_t)r * 64 + k0 + lk] : 0.f;
        }
#pragma unroll
        for (int i = 0; i < 4; i++) {
            int k = wk + i * 4;
            Ws[k][wj] = W2[(size_t)(k0 + k) * COUT + j0 + wj];
        }
        __syncthreads();
#pragma unroll
        for (int kk = 0; kk < 16; kk++) {
            float4 a = *(const float4*)&As[kk][ty * 4];
            float4 b = *(const float4*)&Ws[kk][tx * 4];
            acc[0][0] += a.x * b.x; acc[0][1] += a.x * b.y; acc[0][2] += a.x * b.z; acc[0][3] += a.x * b.w;
            acc[1][0] += a.y * b.x; acc[1][1] += a.y * b.y; acc[1][2] += a.y * b.z; acc[1][3] += a.y * b.w;
            acc[2][0] += a.z * b.x; acc[2][1] += a.z * b.y; acc[2][2] += a.z * b.z; acc[2][3] += a.z * b.w;
            acc[3][0] += a.w * b.x; acc[3][1] += a.w * b.y; acc[3][2] += a.w * b.z; acc[3][3] += a.w * b.w;
        }
        __syncthreads();
    }

    const float4 b2v = *(const float4*)(b2 + j0 + tx * 4);
#pragma unroll
    for (int mi = 0; mi < 4; mi++) {
        int r = row0 + ty * 4 + mi;
        if (r < n) {
            float4 o = make_float4(acc[mi][0] + b2v.x, acc[mi][1] + b2v.y,
                                   acc[mi][2] + b2v.z, acc[mi][3] + b2v.w);
            *(float4*)&y[(size_t)r * S + j0 + tx * 4] = o;
            *(uint4*)&yu[(size_t)r * S + COUT + j0 + tx * 4] =
                make_uint4(SENT, SENT, SENT, SENT);
        }
    }
}

// ---------------- edge max-aggregation (encoded atomicMax) -----------------
template<int C>
__global__ void agg_kernel(const float* __restrict__ y, unsigned* __restrict__ yu,
                           const int* __restrict__ ei, int E)
{
    const int CPV = C / 4;
    int gid = blockIdx.x * blockDim.x + threadIdx.x;
    if (gid >= E * CPV) return;
    int e  = gid / CPV;
    int ch = (gid - e * CPV) * 4;
    int src = __ldg(ei + e);
    int tgt = __ldg(ei + E + e);
    const float4 v = *(const float4*)(y + (size_t)src * (2 * C) + ch);
    unsigned* p = yu + (size_t)tgt * (2 * C) + C + ch;
    atomicMax(p + 0, ordf(v.x));
    atomicMax(p + 1, ordf(v.y));
    atomicMax(p + 2, ordf(v.z));
    atomicMax(p + 3, ordf(v.w));
}

// ---------------- in-place decode of agg half (sentinel -> 0) --------------
template<int C>
__global__ void dec_kernel(float* __restrict__ y, int n)
{
    const int CPV = C / 4;
    int gid = blockIdx.x * blockDim.x + threadIdx.x;
    if (gid >= n * CPV) return;
    int r  = gid / CPV;
    int ch = (gid - r * CPV) * 4;
    unsigned* p = (unsigned*)y + (size_t)r * (2 * C) + C + ch;
    uint4 u = *(uint4*)p;
    float4 f;
    f.x = (u.x == SENT) ? 0.f : unordf(u.x);
    f.y = (u.y == SENT) ? 0.f : unordf(u.y);
    f.z = (u.z == SENT) ? 0.f : unordf(u.z);
    f.w = (u.w == SENT) ? 0.f : unordf(u.w);
    *(float4*)p = f;
}

// ---------------- cluster pooling ------------------------------------------
__global__ void pool_init_kernel(unsigned* __restrict__ pe, int nc)
{
    int gid = blockIdx.x * blockDim.x + threadIdx.x;
    if (gid >= nc * 128) return;
    *(uint4*)(pe + (size_t)gid * 4) = make_uint4(SENT, SENT, SENT, SENT);
}

__global__ void pool_kernel(const float* __restrict__ xf, const int* __restrict__ cluster,
                            unsigned* __restrict__ pe, int n)
{
    int gid = blockIdx.x * blockDim.x + threadIdx.x;
    if (gid >= n * 128) return;
    int nd = gid >> 7;
    int ch = (gid & 127) << 2;
    int cl = __ldg(cluster + nd);
    const float4 v = *(const float4*)(xf + (size_t)nd * 512 + ch);
    unsigned* p = pe + (size_t)cl * 512 + ch;
    atomicMax(p + 0, ordf(v.x));
    atomicMax(p + 1, ordf(v.y));
    atomicMax(p + 2, ordf(v.z));
    atomicMax(p + 3, ordf(v.w));
}

// decode pooled -> out, accumulate per-column sum of squares
__global__ __launch_bounds__(512) void colsq_kernel(const unsigned* __restrict__ pe,
                                                    float* __restrict__ out,
                                                    float* __restrict__ colsq, int nc)
{
    const int ROWS = 50;
    int c  = threadIdx.x;
    int r0 = blockIdx.x * ROWS;
    int r1 = min(r0 + ROWS, nc);
    float s = 0.f;
    for (int r = r0; r < r1; r++) {
        unsigned u = pe[(size_t)r * 512 + c];
        float f = (u == SENT) ? 0.f : unordf(u);
        out[(size_t)r * 512 + c] = f;
        s += f * f;
    }
    atomicAdd(colsq + c, s);
}

__global__ void scale_kernel(float* __restrict__ out, const float* __restrict__ colsq, int nc)
{
    int gid = blockIdx.x * blockDim.x + threadIdx.x;
    if (gid >= nc * 512) return;
    int c = gid & 511;
    out[gid] = out[gid] / sqrtf(__ldg(colsq + c));
}

// ---------------- launch ----------------------------------------------------
extern "C" void kernel_launch(void* const* d_in, const int* in_sizes, int n_in,
                              void* d_out, int out_size)
{
    const float* x       = (const float*)d_in[0];
    const int*   ei      = (const int*)d_in[1];
    const int*   cluster = (const int*)d_in[2];
    const int N  = in_sizes[0] / 64;
    const int E  = in_sizes[1] / 2;
    const int NC = out_size / 512;
    float* out = (float*)d_out;

    float *bufA, *bufB, *hmid, *colsq; unsigned* pe;
    cudaGetSymbolAddress((void**)&bufA,  g_bufA);
    cudaGetSymbolAddress((void**)&bufB,  g_bufB);
    cudaGetSymbolAddress((void**)&hmid,  g_hmid);
    cudaGetSymbolAddress((void**)&pe,    g_pool);
    cudaGetSymbolAddress((void**)&colsq, g_colsq);

    const int gRows = (N + 63) / 64;

    // ---- layer 0: Cin = 64 ----
    {
        const float* W1 = (const float*)d_in[3];
        const float* b1 = (const float*)d_in[4];
        const float* g  = (const float*)d_in[5];
        const float* be = (const float*)d_in[6];
        const float* W2 = (const float*)d_in[7];
        const float* b2 = (const float*)d_in[8];
        mlp1_kernel<64><<<gRows, 256>>>(x, W1, b1, g, be, hmid, N);
        mlp2_kernel<64><<<dim3(gRows, 1), 256>>>(hmid, W2, b2, bufA, (unsigned*)bufA, N);
        agg_kernel<64><<<(E * 16 + 255) / 256, 256>>>(bufA, (unsigned*)bufA, ei, E);
        dec_kernel<64><<<(N * 16 + 255) / 256, 256>>>(bufA, N);
    }
    // ---- layer 1: Cin = 128 ----
    {
        const float* W1 = (const float*)d_in[9];
        const float* b1 = (const float*)d_in[10];
        const float* g  = (const float*)d_in[11];
        const float* be = (const float*)d_in[12];
        const float* W2 = (const float*)d_in[13];
        const float* b2 = (const float*)d_in[14];
        mlp1_kernel<128><<<gRows, 256>>>(bufA, W1, b1, g, be, hmid, N);
        mlp2_kernel<128><<<dim3(gRows, 2), 256>>>(hmid, W2, b2, bufB, (unsigned*)bufB, N);
        agg_kernel<128><<<(E * 32 + 255) / 256, 256>>>(bufB, (unsigned*)bufB, ei, E);
        dec_kernel<128><<<(N * 32 + 255) / 256, 256>>>(bufB, N);
    }
    // ---- layer 2: Cin = 256 ----
    {
        const float* W1 = (const float*)d_in[15];
        const float* b1 = (const float*)d_in[16];
        const float* g  = (const float*)d_in[17];
        const float* be = (const float*)d_in[18];
        const float* W2 = (const float*)d_in[19];
        const float* b2 = (const float*)d_in[20];
        mlp1_kernel<256><<<gRows, 256>>>(bufB, W1, b1, g, be, hmid, N);
        mlp2_kernel<256><<<dim3(gRows, 4), 256>>>(hmid, W2, b2, bufA, (unsigned*)bufA, N);
        agg_kernel<256><<<(E * 64 + 255) / 256, 256>>>(bufA, (unsigned*)bufA, ei, E);
        dec_kernel<256><<<(N * 64 + 255) / 256, 256>>>(bufA, N);
    }
    // ---- cluster max-pool + column L2 normalize ----
    pool_init_kernel<<<(NC * 128 + 255) / 256, 256>>>(pe, NC);
    pool_kernel<<<(N * 128 + 255) / 256, 256>>>(bufA, cluster, pe, N);
    cudaMemsetAsync(colsq, 0, 512 * sizeof(float));
    colsq_kernel<<<(NC + 49) / 50, 512>>>(pe, out, colsq, NC);
    scale_kernel<<<(NC * 512 + 255) / 256, 256>>>(out, colsq, NC);
}

// round 3
// speedup vs baseline: 1.2636x; 1.2636x over previous
#include <cuda_runtime.h>
#include <cstdint>

#define LN_EPS 1e-5f
#define SENT 0x007FFFFFu   // order-encoded -inf

// ---------------- scratch (device globals: allocation-free) ----------------
__device__ float    g_bufA[100000 * 512];   // layer0 out (stride 128) / layer2 out (stride 512)
__device__ float    g_bufB[100000 * 256];   // layer1 out (stride 256)
__device__ float    g_hmid[100000 * 64];    // LN+ReLU intermediate
__device__ unsigned g_pool[10000 * 512];    // encoded cluster-max
__device__ float    g_colsq[512];           // column sum of squares

// ---------------- order-preserving float <-> uint -------------------------
__device__ __forceinline__ unsigned ordf(float f) {
    unsigned u = __float_as_uint(f);
    return (u & 0x80000000u) ? ~u : (u | 0x80000000u);
}
__device__ __forceinline__ float unordf(unsigned e) {
    return __uint_as_float((e & 0x80000000u) ? (e ^ 0x80000000u) : ~e);
}

// ---------------- GEMM1 + bias + LayerNorm + ReLU --------------------------
// h_mid[N,64] = relu(LN(x[N,CIN] @ W1[CIN,64] + b1) * g + be)
template<int CIN>
__global__ __launch_bounds__(256) void mlp1_kernel(
    const float* __restrict__ x, const float* __restrict__ W1,
    const float* __restrict__ b1, const float* __restrict__ gam,
    const float* __restrict__ bet, float* __restrict__ hmid, int n)
{
    __shared__ __align__(16) float As[16][68];
    __shared__ __align__(16) float Ws[16][68];
    const int t  = threadIdx.x;
    const int tx = t & 15, ty = t >> 4;
    const int row0 = blockIdx.x * 64;
    const int lm = t >> 4, lk = t & 15;
    const int wj = t & 63, wk = t >> 6;

    float acc[4][4] = {};

    for (int k0 = 0; k0 < CIN; k0 += 16) {
#pragma unroll
        for (int i = 0; i < 4; i++) {
            int m = lm + i * 16;
            int r = row0 + m;
            As[lk][m] = (r < n) ? x[(size_t)r * CIN + k0 + lk] : 0.f;
        }
#pragma unroll
        for (int i = 0; i < 4; i++) {
            int k = wk + i * 4;
            Ws[k][wj] = W1[(size_t)(k0 + k) * 64 + wj];
        }
        __syncthreads();
#pragma unroll
        for (int kk = 0; kk < 16; kk++) {
            float4 a = *(const float4*)&As[kk][ty * 4];
            float4 b = *(const float4*)&Ws[kk][tx * 4];
            acc[0][0] += a.x * b.x; acc[0][1] += a.x * b.y; acc[0][2] += a.x * b.z; acc[0][3] += a.x * b.w;
            acc[1][0] += a.y * b.x; acc[1][1] += a.y * b.y; acc[1][2] += a.y * b.z; acc[1][3] += a.y * b.w;
            acc[2][0] += a.z * b.x; acc[2][1] += a.z * b.y; acc[2][2] += a.z * b.z; acc[2][3] += a.z * b.w;
            acc[3][0] += a.w * b.x; acc[3][1] += a.w * b.y; acc[3][2] += a.w * b.z; acc[3][3] += a.w * b.w;
        }
        __syncthreads();
    }

    const float4 b1v = *(const float4*)(b1  + tx * 4);
    const float4 gv  = *(const float4*)(gam + tx * 4);
    const float4 bev = *(const float4*)(bet + tx * 4);

#pragma unroll
    for (int mi = 0; mi < 4; mi++) {
        float v0 = acc[mi][0] + b1v.x, v1 = acc[mi][1] + b1v.y;
        float v2 = acc[mi][2] + b1v.z, v3 = acc[mi][3] + b1v.w;
        float s = v0 + v1 + v2 + v3;
        float q = v0 * v0 + v1 * v1 + v2 * v2 + v3 * v3;
#pragma unroll
        for (int off = 1; off < 16; off <<= 1) {
            s += __shfl_xor_sync(0xffffffffu, s, off);
            q += __shfl_xor_sync(0xffffffffu, q, off);
        }
        float mu  = s * (1.0f / 64.0f);
        float var = q * (1.0f / 64.0f) - mu * mu;
        float rs  = rsqrtf(var + LN_EPS);
        v0 = fmaxf((v0 - mu) * rs * gv.x + bev.x, 0.f);
        v1 = fmaxf((v1 - mu) * rs * gv.y + bev.y, 0.f);
        v2 = fmaxf((v2 - mu) * rs * gv.z + bev.z, 0.f);
        v3 = fmaxf((v3 - mu) * rs * gv.w + bev.w, 0.f);
        int r = row0 + ty * 4 + mi;
        if (r < n)
            *(float4*)&hmid[(size_t)r * 64 + tx * 4] = make_float4(v0, v1, v2, v3);
    }
}

// ---------------- GEMM2 + bias, and seed agg-half with sentinel ------------
// y[:, 0:COUT] = hmid @ W2[64,COUT] + b2 ; yu[:, COUT:2*COUT] = SENT
template<int COUT>
__global__ __launch_bounds__(256) void mlp2_kernel(
    const float* __restrict__ hmid, const float* __restrict__ W2,
    const float* __restrict__ b2, float* __restrict__ y,
    unsigned* __restrict__ yu, int n)
{
    __shared__ __align__(16) float As[16][68];
    __shared__ __align__(16) float Ws[16][68];
    const int t  = threadIdx.x;
    const int tx = t & 15, ty = t >> 4;
    const int row0 = blockIdx.x * 64;
    const int j0   = blockIdx.y * 64;
    const int S = 2 * COUT;
    const int lm = t >> 4, lk = t & 15;
    const int wj = t & 63, wk = t >> 6;

    float acc[4][4] = {};

#pragma unroll
    for (int k0 = 0; k0 < 64; k0 += 16) {
#pragma unroll
        for (int i = 0; i < 4; i++) {
            int m = lm + i * 16;
            int r = row0 + m;
            As[lk][m] = (r < n) ? hmid[(size_t)r * 64 + k0 + lk] : 0.f;
        }
#pragma unroll
        for (int i = 0; i < 4; i++) {
            int k = wk + i * 4;
            Ws[k][wj] = W2[(size_t)(k0 + k) * COUT + j0 + wj];
        }
        __syncthreads();
#pragma unroll
        for (int kk = 0; kk < 16; kk++) {
            float4 a = *(const float4*)&As[kk][ty * 4];
            float4 b = *(const float4*)&Ws[kk][tx * 4];
            acc[0][0] += a.x * b.x; acc[0][1] += a.x * b.y; acc[0][2] += a.x * b.z; acc[0][3] += a.x * b.w;
            acc[1][0] += a.y * b.x; acc[1][1] += a.y * b.y; acc[1][2] += a.y * b.z; acc[1][3] += a.y * b.w;
            acc[2][0] += a.z * b.x; acc[2][1] += a.z * b.y; acc[2][2] += a.z * b.z; acc[2][3] += a.z * b.w;
            acc[3][0] += a.w * b.x; acc[3][1] += a.w * b.y; acc[3][2] += a.w * b.z; acc[3][3] += a.w * b.w;
        }
        __syncthreads();
    }

    const float4 b2v = *(const float4*)(b2 + j0 + tx * 4);
#pragma unroll
    for (int mi = 0; mi < 4; mi++) {
        int r = row0 + ty * 4 + mi;
        if (r < n) {
            float4 o = make_float4(acc[mi][0] + b2v.x, acc[mi][1] + b2v.y,
                                   acc[mi][2] + b2v.z, acc[mi][3] + b2v.w);
            *(float4*)&y[(size_t)r * S + j0 + tx * 4] = o;
            *(uint4*)&yu[(size_t)r * S + COUT + j0 + tx * 4] =
                make_uint4(SENT, SENT, SENT, SENT);
        }
    }
}

// ---------------- edge max-aggregation (encoded atomicMax) -----------------
template<int C>
__global__ void agg_kernel(const float* __restrict__ y, unsigned* __restrict__ yu,
                           const int* __restrict__ ei, int E)
{
    const int CPV = C / 4;
    int gid = blockIdx.x * blockDim.x + threadIdx.x;
    if (gid >= E * CPV) return;
    int e  = gid / CPV;
    int ch = (gid - e * CPV) * 4;
    int src = __ldg(ei + e);
    int tgt = __ldg(ei + E + e);
    const float4 v = *(const float4*)(y + (size_t)src * (2 * C) + ch);
    unsigned* p = yu + (size_t)tgt * (2 * C) + C + ch;
    atomicMax(p + 0, ordf(v.x));
    atomicMax(p + 1, ordf(v.y));
    atomicMax(p + 2, ordf(v.z));
    atomicMax(p + 3, ordf(v.w));
}

// ---------------- in-place decode of agg half (sentinel -> 0) --------------
template<int C>
__global__ void dec_kernel(float* __restrict__ y, int n)
{
    const int CPV = C / 4;
    int gid = blockIdx.x * blockDim.x + threadIdx.x;
    if (gid >= n * CPV) return;
    int r  = gid / CPV;
    int ch = (gid - r * CPV) * 4;
    unsigned* p = (unsigned*)y + (size_t)r * (2 * C) + C + ch;
    uint4 u = *(uint4*)p;
    float4 f;
    f.x = (u.x == SENT) ? 0.f : unordf(u.x);
    f.y = (u.y == SENT) ? 0.f : unordf(u.y);
    f.z = (u.z == SENT) ? 0.f : unordf(u.z);
    f.w = (u.w == SENT) ? 0.f : unordf(u.w);
    *(float4*)p = f;
}

// ---------------- cluster pooling ------------------------------------------
__global__ void pool_init_kernel(unsigned* __restrict__ pe, int nc)
{
    int gid = blockIdx.x * blockDim.x + threadIdx.x;
    if (gid >= nc * 128) return;
    *(uint4*)(pe + (size_t)gid * 4) = make_uint4(SENT, SENT, SENT, SENT);
}

__global__ void pool_kernel(const float* __restrict__ xf, const int* __restrict__ cluster,
                            unsigned* __restrict__ pe, int n)
{
    int gid = blockIdx.x * blockDim.x + threadIdx.x;
    if (gid >= n * 128) return;
    int nd = gid >> 7;
    int ch = (gid & 127) << 2;
    int cl = __ldg(cluster + nd);
    const float4 v = *(const float4*)(xf + (size_t)nd * 512 + ch);
    unsigned* p = pe + (size_t)cl * 512 + ch;
    atomicMax(p + 0, ordf(v.x));
    atomicMax(p + 1, ordf(v.y));
    atomicMax(p + 2, ordf(v.z));
    atomicMax(p + 3, ordf(v.w));
}

// decode pooled -> out, accumulate per-column sum of squares
__global__ __launch_bounds__(512) void colsq_kernel(const unsigned* __restrict__ pe,
                                                    float* __restrict__ out,
                                                    float* __restrict__ colsq, int nc)
{
    const int ROWS = 50;
    int c  = threadIdx.x;
    int r0 = blockIdx.x * ROWS;
    int r1 = min(r0 + ROWS, nc);
    float s = 0.f;
    for (int r = r0; r < r1; r++) {
        unsigned u = pe[(size_t)r * 512 + c];
        float f = (u == SENT) ? 0.f : unordf(u);
        out[(size_t)r * 512 + c] = f;
        s += f * f;
    }
    atomicAdd(colsq + c, s);
}

__global__ void scale_kernel(float* __restrict__ out, const float* __restrict__ colsq, int nc)
{
    int gid = blockIdx.x * blockDim.x + threadIdx.x;
    if (gid >= nc * 512) return;
    int c = gid & 511;
    out[gid] = out[gid] / sqrtf(__ldg(colsq + c));
}

// ---------------- launch ----------------------------------------------------
extern "C" void kernel_launch(void* const* d_in, const int* in_sizes, int n_in,
                              void* d_out, int out_size)
{
    const float* x       = (const float*)d_in[0];
    const int*   ei      = (const int*)d_in[1];
    const int*   cluster = (const int*)d_in[2];
    const int N  = in_sizes[0] / 64;
    const int E  = in_sizes[1] / 2;
    const int NC = out_size / 512;
    float* out = (float*)d_out;

    float *bufA, *bufB, *hmid, *colsq; unsigned* pe;
    cudaGetSymbolAddress((void**)&bufA,  g_bufA);
    cudaGetSymbolAddress((void**)&bufB,  g_bufB);
    cudaGetSymbolAddress((void**)&hmid,  g_hmid);
    cudaGetSymbolAddress((void**)&pe,    g_pool);
    cudaGetSymbolAddress((void**)&colsq, g_colsq);

    const int gRows = (N + 63) / 64;

    // ---- layer 0: Cin = 64 ----
    {
        const float* W1 = (const float*)d_in[3];
        const float* b1 = (const float*)d_in[4];
        const float* g  = (const float*)d_in[5];
        const float* be = (const float*)d_in[6];
        const float* W2 = (const float*)d_in[7];
        const float* b2 = (const float*)d_in[8];
        mlp1_kernel<64><<<gRows, 256>>>(x, W1, b1, g, be, hmid, N);
        mlp2_kernel<64><<<dim3(gRows, 1), 256>>>(hmid, W2, b2, bufA, (unsigned*)bufA, N);
        agg_kernel<64><<<(E * 16 + 255) / 256, 256>>>(bufA, (unsigned*)bufA, ei, E);
        dec_kernel<64><<<(N * 16 + 255) / 256, 256>>>(bufA, N);
    }
    // ---- layer 1: Cin = 128 ----
    {
        const float* W1 = (const float*)d_in[9];
        const float* b1 = (const float*)d_in[10];
        const float* g  = (const float*)d_in[11];
        const float* be = (const float*)d_in[12];
        const float* W2 = (const float*)d_in[13];
        const float* b2 = (const float*)d_in[14];
        mlp1_kernel<128><<<gRows, 256>>>(bufA, W1, b1, g, be, hmid, N);
        mlp2_kernel<128><<<dim3(gRows, 2), 256>>>(hmid, W2, b2, bufB, (unsigned*)bufB, N);
        agg_kernel<128><<<(E * 32 + 255) / 256, 256>>>(bufB, (unsigned*)bufB, ei, E);
        dec_kernel<128><<<(N * 32 + 255) / 256, 256>>>(bufB, N);
    }
    // ---- layer 2: Cin = 256 ----
    {
        const float* W1 = (const float*)d_in[15];
        const float* b1 = (const float*)d_in[16];
        const float* g  = (const float*)d_in[17];
        const float* be = (const float*)d_in[18];
        const float* W2 = (const float*)d_in[19];
        const float* b2 = (const float*)d_in[20];
        mlp1_kernel<256><<<gRows, 256>>>(bufB, W1, b1, g, be, hmid, N);
        mlp2_kernel<256><<<dim3(gRows, 4), 256>>>(hmid, W2, b2, bufA, (unsigned*)bufA, N);
        agg_kernel<256><<<(E * 64 + 255) / 256, 256>>>(bufA, (unsigned*)bufA, ei, E);
        dec_kernel<256><<<(N * 64 + 255) / 256, 256>>>(bufA, N);
    }
    // ---- cluster max-pool + column L2 normalize ----
    pool_init_kernel<<<(NC * 128 + 255) / 256, 256>>>(pe, NC);
    pool_kernel<<<(N * 128 + 255) / 256, 256>>>(bufA, cluster, pe, N);
    cudaMemsetAsync(colsq, 0, 512 * sizeof(float));
    colsq_kernel<<<(NC + 49) / 50, 512>>>(pe, out, colsq, NC);
    scale_kernel<<<(NC * 512 + 255) / 256, 256>>>(out, colsq, NC);
}

// round 4
// speedup vs baseline: 2.7751x; 2.1962x over previous
#include <cuda_runtime.h>
#include <cstdint>

#define LN_EPS 1e-5f

// ---------------- scratch (device globals: allocation-free) ----------------
__device__ float g_bufA[100000 * 512];   // layer0 out (stride 128) / layer2 out (stride 512)
__device__ float g_bufB[100000 * 256];   // layer1 out (stride 256)
__device__ float g_hmid[100000 * 64];    // LN+ReLU intermediate
__device__ float g_colsq[512];           // column sum of squares

// CSR scratch
__device__ int g_deg[100000];            // in-degree per node
__device__ int g_rowptr[100000];         // exclusive prefix of deg
__device__ int g_cursor[100000];
__device__ int g_esrc[800000];           // CSR edge source indices
__device__ int g_cdeg[10000];            // nodes per cluster
__device__ int g_cptr[10000];
__device__ int g_ccur[10000];
__device__ int g_cnodes[100000];         // CSR node indices per cluster
__device__ int g_bsumsN[512];
__device__ int g_bsumsC[512];

__device__ __forceinline__ float neg_inf() { return __int_as_float(0xff800000); }

// ---------------- CSR build --------------------------------------------------
__global__ void hist_edges(const int* __restrict__ ei, int E, int* __restrict__ deg)
{
    int e = blockIdx.x * blockDim.x + threadIdx.x;
    if (e < E) atomicAdd(&deg[__ldg(ei + E + e)], 1);
}

__global__ void hist_nodes(const int* __restrict__ cluster, int n, int* __restrict__ cdeg)
{
    int i = blockIdx.x * blockDim.x + threadIdx.x;
    if (i < n) atomicAdd(&cdeg[__ldg(cluster + i)], 1);
}

__global__ __launch_bounds__(512) void scan_block(const int* __restrict__ in,
                                                  int* __restrict__ out,
                                                  int* __restrict__ sums, int n)
{
    __shared__ int s[512];
    int tid = threadIdx.x;
    int i = blockIdx.x * 512 + tid;
    int v = (i < n) ? in[i] : 0;
    s[tid] = v;
    __syncthreads();
#pragma unroll
    for (int off = 1; off < 512; off <<= 1) {
        int t = (tid >= off) ? s[tid - off] : 0;
        __syncthreads();
        s[tid] += t;
        __syncthreads();
    }
    if (i < n) out[i] = s[tid] - v;              // exclusive
    if (tid == 511) sums[blockIdx.x] = s[511];
}

__global__ __launch_bounds__(256) void scan_sums(int* __restrict__ sums, int nb)
{
    __shared__ int s[256];
    int tid = threadIdx.x;
    int v = (tid < nb) ? sums[tid] : 0;
    s[tid] = v;
    __syncthreads();
#pragma unroll
    for (int off = 1; off < 256; off <<= 1) {
        int t = (tid >= off) ? s[tid - off] : 0;
        __syncthreads();
        s[tid] += t;
        __syncthreads();
    }
    if (tid < nb) sums[tid] = s[tid] - v;        // exclusive block offsets
}

__global__ __launch_bounds__(512) void scan_add(int* __restrict__ out,
                                                const int* __restrict__ sums, int n)
{
    int i = blockIdx.x * 512 + threadIdx.x;
    if (i < n) out[i] += sums[blockIdx.x];
}

__global__ void scatter_edges(const int* __restrict__ ei, int E,
                              const int* __restrict__ rowptr, int* __restrict__ cursor,
                              int* __restrict__ esrc)
{
    int e = blockIdx.x * blockDim.x + threadIdx.x;
    if (e >= E) return;
    int src = __ldg(ei + e);
    int tgt = __ldg(ei + E + e);
    int pos = rowptr[tgt] + atomicAdd(&cursor[tgt], 1);
    esrc[pos] = src;
}

__global__ void scatter_nodes(const int* __restrict__ cluster, int n,
                              const int* __restrict__ cptr, int* __restrict__ ccur,
                              int* __restrict__ cnodes)
{
    int i = blockIdx.x * blockDim.x + threadIdx.x;
    if (i >= n) return;
    int cl = __ldg(cluster + i);
    int pos = cptr[cl] + atomicAdd(&ccur[cl], 1);
    cnodes[pos] = i;
}

// ---------------- GEMM1 + bias + LayerNorm + ReLU --------------------------
template<int CIN>
__global__ __launch_bounds__(256) void mlp1_kernel(
    const float* __restrict__ x, const float* __restrict__ W1,
    const float* __restrict__ b1, const float* __restrict__ gam,
    const float* __restrict__ bet, float* __restrict__ hmid, int n)
{
    __shared__ __align__(16) float As[16][68];
    __shared__ __align__(16) float Ws[16][68];
    const int t  = threadIdx.x;
    const int tx = t & 15, ty = t >> 4;
    const int row0 = blockIdx.x * 64;
    const int lm = t >> 4, lk = t & 15;
    const int wj = t & 63, wk = t >> 6;

    float acc[4][4] = {};

    for (int k0 = 0; k0 < CIN; k0 += 16) {
#pragma unroll
        for (int i = 0; i < 4; i++) {
            int m = lm + i * 16;
            int r = row0 + m;
            As[lk][m] = (r < n) ? x[(size_t)r * CIN + k0 + lk] : 0.f;
        }
#pragma unroll
        for (int i = 0; i < 4; i++) {
            int k = wk + i * 4;
            Ws[k][wj] = W1[(size_t)(k0 + k) * 64 + wj];
        }
        __syncthreads();
#pragma unroll
        for (int kk = 0; kk < 16; kk++) {
            float4 a = *(const float4*)&As[kk][ty * 4];
            float4 b = *(const float4*)&Ws[kk][tx * 4];
            acc[0][0] += a.x * b.x; acc[0][1] += a.x * b.y; acc[0][2] += a.x * b.z; acc[0][3] += a.x * b.w;
            acc[1][0] += a.y * b.x; acc[1][1] += a.y * b.y; acc[1][2] += a.y * b.z; acc[1][3] += a.y * b.w;
            acc[2][0] += a.z * b.x; acc[2][1] += a.z * b.y; acc[2][2] += a.z * b.z; acc[2][3] += a.z * b.w;
            acc[3][0] += a.w * b.x; acc[3][1] += a.w * b.y; acc[3][2] += a.w * b.z; acc[3][3] += a.w * b.w;
        }
        __syncthreads();
    }

    const float4 b1v = *(const float4*)(b1  + tx * 4);
    const float4 gv  = *(const float4*)(gam + tx * 4);
    const float4 bev = *(const float4*)(bet + tx * 4);

#pragma unroll
    for (int mi = 0; mi < 4; mi++) {
        float v0 = acc[mi][0] + b1v.x, v1 = acc[mi][1] + b1v.y;
        float v2 = acc[mi][2] + b1v.z, v3 = acc[mi][3] + b1v.w;
        float s = v0 + v1 + v2 + v3;
        float q = v0 * v0 + v1 * v1 + v2 * v2 + v3 * v3;
#pragma unroll
        for (int off = 1; off < 16; off <<= 1) {
            s += __shfl_xor_sync(0xffffffffu, s, off);
            q += __shfl_xor_sync(0xffffffffu, q, off);
        }
        float mu  = s * (1.0f / 64.0f);
        float var = q * (1.0f / 64.0f) - mu * mu;
        float rs  = rsqrtf(var + LN_EPS);
        v0 = fmaxf((v0 - mu) * rs * gv.x + bev.x, 0.f);
        v1 = fmaxf((v1 - mu) * rs * gv.y + bev.y, 0.f);
        v2 = fmaxf((v2 - mu) * rs * gv.z + bev.z, 0.f);
        v3 = fmaxf((v3 - mu) * rs * gv.w + bev.w, 0.f);
        int r = row0 + ty * 4 + mi;
        if (r < n)
            *(float4*)&hmid[(size_t)r * 64 + tx * 4] = make_float4(v0, v1, v2, v3);
    }
}

// ---------------- GEMM2 + bias (writes first half of concat buffer) --------
template<int COUT>
__global__ __launch_bounds__(256) void mlp2_kernel(
    const float* __restrict__ hmid, const float* __restrict__ W2,
    const float* __restrict__ b2, float* __restrict__ y, int n)
{
    __shared__ __align__(16) float As[16][68];
    __shared__ __align__(16) float Ws[16][68];
    const int t  = threadIdx.x;
    const int tx = t & 15, ty = t >> 4;
    const int row0 = blockIdx.x * 64;
    const int j0   = blockIdx.y * 64;
    const int S = 2 * COUT;
    const int lm = t >> 4, lk = t & 15;
    const int wj = t & 63, wk = t >> 6;

    float acc[4][4] = {};

#pragma unroll
    for (int k0 = 0; k0 < 64; k0 += 16) {
#pragma unroll
        for (int i = 0; i < 4; i++) {
            int m = lm + i * 16;
            int r = row0 + m;
            As[lk][m] = (r < n) ? hmid[(size_t)r * 64 + k0 + lk] : 0.f;
        }
#pragma unroll
        for (int i = 0; i < 4; i++) {
            int k = wk + i * 4;
            Ws[k][wj] = W2[(size_t)(k0 + k) * COUT + j0 + wj];
        }
        __syncthreads();
#pragma unroll
        for (int kk = 0; kk < 16; kk++) {
            float4 a = *(const float4*)&As[kk][ty * 4];
            float4 b = *(const float4*)&Ws[kk][tx * 4];
            acc[0][0] += a.x * b.x; acc[0][1] += a.x * b.y; acc[0][2] += a.x * b.z; acc[0][3] += a.x * b.w;
            acc[1][0] += a.y * b.x; acc[1][1] += a.y * b.y; acc[1][2] += a.y * b.z; acc[1][3] += a.y * b.w;
            acc[2][0] += a.z * b.x; acc[2][1] += a.z * b.y; acc[2][2] += a.z * b.z; acc[2][3] += a.z * b.w;
            acc[3][0] += a.w * b.x; acc[3][1] += a.w * b.y; acc[3][2] += a.w * b.z; acc[3][3] += a.w * b.w;
        }
        __syncthreads();
    }

    const float4 b2v = *(const float4*)(b2 + j0 + tx * 4);
#pragma unroll
    for (int mi = 0; mi < 4; mi++) {
        int r = row0 + ty * 4 + mi;
        if (r < n) {
            float4 o = make_float4(acc[mi][0] + b2v.x, acc[mi][1] + b2v.y,
                                   acc[mi][2] + b2v.z, acc[mi][3] + b2v.w);
            *(float4*)&y[(size_t)r * S + j0 + tx * 4] = o;
        }
    }
}

// ---------------- CSR gather-max aggregation --------------------------------
// warp per target node; lanes own C/32 channels; write y[:, C:2C]
template<int C>
__global__ __launch_bounds__(256) void agg_csr(
    float* __restrict__ y, const int* __restrict__ rowptr,
    const int* __restrict__ deg, const int* __restrict__ esrc, int n)
{
    int w = (blockIdx.x * blockDim.x + threadIdx.x) >> 5;
    if (w >= n) return;
    const int lane = threadIdx.x & 31;
    const int FPL = C / 32;
    int d    = __ldg(deg + w);
    int base = __ldg(rowptr + w);
    float mx[FPL];
#pragma unroll
    for (int i = 0; i < FPL; i++) mx[i] = neg_inf();
    for (int j = 0; j < d; j++) {
        int src = __ldg(esrc + base + j);
        const float* row = y + (size_t)src * (2 * C);
#pragma unroll
        for (int i = 0; i < FPL; i++)
            mx[i] = fmaxf(mx[i], __ldg(row + lane + i * 32));
    }
    float* outp = y + (size_t)w * (2 * C) + C;
#pragma unroll
    for (int i = 0; i < FPL; i++)
        outp[lane + i * 32] = d ? mx[i] : 0.f;
}

// ---------------- CSR cluster max-pool --------------------------------------
// one block (128 threads) per cluster; 4 channels per thread
__global__ __launch_bounds__(128) void pool_csr(
    const float* __restrict__ xf, const int* __restrict__ cptr,
    const int* __restrict__ cdeg, const int* __restrict__ cnodes,
    float* __restrict__ out)
{
    int cl = blockIdx.x;
    int ch = threadIdx.x * 4;
    int d    = __ldg(cdeg + cl);
    int base = __ldg(cptr + cl);
    float4 mx = make_float4(neg_inf(), neg_inf(), neg_inf(), neg_inf());
    for (int j = 0; j < d; j++) {
        int nd = __ldg(cnodes + base + j);
        const float4 v = *(const float4*)(xf + (size_t)nd * 512 + ch);
        mx.x = fmaxf(mx.x, v.x); mx.y = fmaxf(mx.y, v.y);
        mx.z = fmaxf(mx.z, v.z); mx.w = fmaxf(mx.w, v.w);
    }
    float4 r = d ? mx : make_float4(0.f, 0.f, 0.f, 0.f);
    *(float4*)(out + (size_t)cl * 512 + ch) = r;
}

// ---------------- column L2 normalize ---------------------------------------
__global__ __launch_bounds__(512) void colsq_kernel(const float* __restrict__ out,
                                                    float* __restrict__ colsq, int nc)
{
    const int ROWS = 50;
    int c  = threadIdx.x;
    int r0 = blockIdx.x * ROWS;
    int r1 = min(r0 + ROWS, nc);
    float s = 0.f;
    for (int r = r0; r < r1; r++) {
        float f = out[(size_t)r * 512 + c];
        s += f * f;
    }
    atomicAdd(colsq + c, s);
}

__global__ void scale_kernel(float* __restrict__ out, const float* __restrict__ colsq, int nc)
{
    int gid = blockIdx.x * blockDim.x + threadIdx.x;
    if (gid >= nc * 512) return;
    int c = gid & 511;
    out[gid] = out[gid] / sqrtf(__ldg(colsq + c));
}

// ---------------- launch ----------------------------------------------------
extern "C" void kernel_launch(void* const* d_in, const int* in_sizes, int n_in,
                              void* d_out, int out_size)
{
    const float* x       = (const float*)d_in[0];
    const int*   ei      = (const int*)d_in[1];
    const int*   cluster = (const int*)d_in[2];
    const int N  = in_sizes[0] / 64;
    const int E  = in_sizes[1] / 2;
    const int NC = out_size / 512;
    float* out = (float*)d_out;

    float *bufA, *bufB, *hmid, *colsq;
    int *deg, *rowptr, *cursor, *esrc, *cdeg, *cptr, *ccur, *cnodes, *bsumsN, *bsumsC;
    cudaGetSymbolAddress((void**)&bufA,   g_bufA);
    cudaGetSymbolAddress((void**)&bufB,   g_bufB);
    cudaGetSymbolAddress((void**)&hmid,   g_hmid);
    cudaGetSymbolAddress((void**)&colsq,  g_colsq);
    cudaGetSymbolAddress((void**)&deg,    g_deg);
    cudaGetSymbolAddress((void**)&rowptr, g_rowptr);
    cudaGetSymbolAddress((void**)&cursor, g_cursor);
    cudaGetSymbolAddress((void**)&esrc,   g_esrc);
    cudaGetSymbolAddress((void**)&cdeg,   g_cdeg);
    cudaGetSymbolAddress((void**)&cptr,   g_cptr);
    cudaGetSymbolAddress((void**)&ccur,   g_ccur);
    cudaGetSymbolAddress((void**)&cnodes, g_cnodes);
    cudaGetSymbolAddress((void**)&bsumsN, g_bsumsN);
    cudaGetSymbolAddress((void**)&bsumsC, g_bsumsC);

    const int gRows = (N + 63) / 64;
    const int nbN = (N + 511) / 512;
    const int nbC = (NC + 511) / 512;

    // ---- build CSR (targets<-edges, clusters<-nodes) ----
    cudaMemsetAsync(deg,    0, N  * sizeof(int));
    cudaMemsetAsync(cursor, 0, N  * sizeof(int));
    cudaMemsetAsync(cdeg,   0, NC * sizeof(int));
    cudaMemsetAsync(ccur,   0, NC * sizeof(int));
    hist_edges<<<(E + 255) / 256, 256>>>(ei, E, deg);
    hist_nodes<<<(N + 255) / 256, 256>>>(cluster, N, cdeg);
    scan_block<<<nbN, 512>>>(deg, rowptr, bsumsN, N);
    scan_sums<<<1, 256>>>(bsumsN, nbN);
    scan_add<<<nbN, 512>>>(rowptr, bsumsN, N);
    scan_block<<<nbC, 512>>>(cdeg, cptr, bsumsC, NC);
    scan_sums<<<1, 256>>>(bsumsC, nbC);
    scan_add<<<nbC, 512>>>(cptr, bsumsC, NC);
    scatter_edges<<<(E + 255) / 256, 256>>>(ei, E, rowptr, cursor, esrc);
    scatter_nodes<<<(N + 255) / 256, 256>>>(cluster, N, cptr, ccur, cnodes);

    // ---- layer 0: Cin = 64 ----
    {
        const float* W1 = (const float*)d_in[3];
        const float* b1 = (const float*)d_in[4];
        const float* g  = (const float*)d_in[5];
        const float* be = (const float*)d_in[6];
        const float* W2 = (const float*)d_in[7];
        const float* b2 = (const float*)d_in[8];
        mlp1_kernel<64><<<gRows, 256>>>(x, W1, b1, g, be, hmid, N);
        mlp2_kernel<64><<<dim3(gRows, 1), 256>>>(hmid, W2, b2, bufA, N);
        agg_csr<64><<<(N * 32 + 255) / 256, 256>>>(bufA, rowptr, deg, esrc, N);
    }
    // ---- layer 1: Cin = 128 ----
    {
        const float* W1 = (const float*)d_in[9];
        const float* b1 = (const float*)d_in[10];
        const float* g  = (const float*)d_in[11];
        const float* be = (const float*)d_in[12];
        const float* W2 = (const float*)d_in[13];
        const float* b2 = (const float*)d_in[14];
        mlp1_kernel<128><<<gRows, 256>>>(bufA, W1, b1, g, be, hmid, N);
        mlp2_kernel<128><<<dim3(gRows, 2), 256>>>(hmid, W2, b2, bufB, N);
        agg_csr<128><<<(N * 32 + 255) / 256, 256>>>(bufB, rowptr, deg, esrc, N);
    }
    // ---- layer 2: Cin = 256 ----
    {
        const float* W1 = (const float*)d_in[15];
        const float* b1 = (const float*)d_in[16];
        const float* g  = (const float*)d_in[17];
        const float* be = (const float*)d_in[18];
        const float* W2 = (const float*)d_in[19];
        const float* b2 = (const float*)d_in[20];
        mlp1_kernel<256><<<gRows, 256>>>(bufB, W1, b1, g, be, hmid, N);
        mlp2_kernel<256><<<dim3(gRows, 4), 256>>>(hmid, W2, b2, bufA, N);
        agg_csr<256><<<(N * 32 + 255) / 256, 256>>>(bufA, rowptr, deg, esrc, N);
    }
    // ---- cluster max-pool + column L2 normalize ----
    pool_csr<<<NC, 128>>>(bufA, cptr, cdeg, cnodes, out);
    cudaMemsetAsync(colsq, 0, 512 * sizeof(float));
    colsq_kernel<<<(NC + 49) / 50, 512>>>(out, colsq, NC);
    scale_kernel<<<(NC * 512 + 255) / 256, 256>>>(out, colsq, NC);
}

// round 6
// speedup vs baseline: 3.0201x; 1.0883x over previous
#include <cuda_runtime.h>
#include <cuda_bf16.h>
#include <cstdint>

#define LN_EPS 1e-5f

// ---------------- scratch (device globals: allocation-free) ----------------
__device__ __align__(128) __nv_bfloat16 g_xhi[100000 * 64],  g_xlo[100000 * 64];
__device__ __align__(128) __nv_bfloat16 g_hhi[100000 * 64],  g_hlo[100000 * 64];
__device__ __align__(128) __nv_bfloat16 g_y0hi[100000 * 128], g_y0lo[100000 * 128];
__device__ __align__(128) __nv_bfloat16 g_y1hi[100000 * 256], g_y1lo[100000 * 256];
__device__ __align__(128) __nv_bfloat16 g_y2hi[100000 * 512], g_y2lo[100000 * 512];
__device__ __align__(128) __nv_bfloat16 g_w1thi0[64*64],  g_w1tlo0[64*64];
__device__ __align__(128) __nv_bfloat16 g_w1thi1[64*128], g_w1tlo1[64*128];
__device__ __align__(128) __nv_bfloat16 g_w1thi2[64*256], g_w1tlo2[64*256];
__device__ __align__(128) __nv_bfloat16 g_w2thi0[64*64],  g_w2tlo0[64*64];
__device__ __align__(128) __nv_bfloat16 g_w2thi1[128*64], g_w2tlo1[128*64];
__device__ __align__(128) __nv_bfloat16 g_w2thi2[256*64], g_w2tlo2[256*64];
__device__ float g_colsq[512];

// CSR scratch
__device__ int g_deg[100000];
__device__ int g_rowptr[100000];
__device__ int g_cursor[100000];
__device__ int g_esrc[800000];
__device__ int g_cdeg[10000];
__device__ int g_cptr[10000];
__device__ int g_ccur[10000];
__device__ int g_cnodes[100000];
__device__ int g_bsumsN[512];
__device__ int g_bsumsC[512];

__device__ __forceinline__ float neg_inf() { return __int_as_float(0xff800000); }

// fp32 pair -> (bf16 hi, bf16 lo) packed words (low half = first value)
__device__ __forceinline__ void split2(float a, float b, uint32_t& hi, uint32_t& lo) {
    __nv_bfloat16 ah = __float2bfloat16_rn(a);
    __nv_bfloat16 bh = __float2bfloat16_rn(b);
    __nv_bfloat16 al = __float2bfloat16_rn(a - __bfloat162float(ah));
    __nv_bfloat16 bl = __float2bfloat16_rn(b - __bfloat162float(bh));
    __nv_bfloat162 h = __halves2bfloat162(ah, bh);
    __nv_bfloat162 l = __halves2bfloat162(al, bl);
    hi = *reinterpret_cast<uint32_t*>(&h);
    lo = *reinterpret_cast<uint32_t*>(&l);
}

// mma.sync m16n8k16 bf16 (row.col), fp32 accumulate in-place
__device__ __forceinline__ void mma16816(float* c, uint32_t a0, uint32_t a1,
                                         uint32_t a2, uint32_t a3,
                                         uint32_t b0, uint32_t b1) {
    asm volatile(
        "mma.sync.aligned.m16n8k16.row.col.f32.bf16.bf16.f32 "
        "{%0,%1,%2,%3}, {%4,%5,%6,%7}, {%8,%9}, {%0,%1,%2,%3};"
        : "+f"(c[0]), "+f"(c[1]), "+f"(c[2]), "+f"(c[3])
        : "r"(a0), "r"(a1), "r"(a2), "r"(a3), "r"(b0), "r"(b1));
}

// ---------------- conversion kernels ----------------------------------------
__global__ void conv_split(const float* __restrict__ in, __nv_bfloat16* __restrict__ hi,
                           __nv_bfloat16* __restrict__ lo, int n)
{
    int i = blockIdx.x * blockDim.x + threadIdx.x;
    if (i >= n) return;
    float v = __ldg(in + i);
    __nv_bfloat16 h = __float2bfloat16_rn(v);
    hi[i] = h;
    lo[i] = __float2bfloat16_rn(v - __bfloat162float(h));
}

// in [K, M] row-major -> out [M, K] (transposed), split
__global__ void conv_split_T(const float* __restrict__ in, __nv_bfloat16* __restrict__ hi,
                             __nv_bfloat16* __restrict__ lo, int K, int M)
{
    int g = blockIdx.x * blockDim.x + threadIdx.x;
    if (g >= K * M) return;
    int k = g / M, m = g - k * M;
    float v = __ldg(in + g);
    __nv_bfloat16 h = __float2bfloat16_rn(v);
    hi[m * K + k] = h;
    lo[m * K + k] = __float2bfloat16_rn(v - __bfloat162float(h));
}

// ---------------- CSR build --------------------------------------------------
__global__ void hist_edges(const int* __restrict__ ei, int E, int* __restrict__ deg)
{
    int e = blockIdx.x * blockDim.x + threadIdx.x;
    if (e < E) atomicAdd(&deg[__ldg(ei + E + e)], 1);
}

__global__ void hist_nodes(const int* __restrict__ cluster, int n, int* __restrict__ cdeg)
{
    int i = blockIdx.x * blockDim.x + threadIdx.x;
    if (i < n) atomicAdd(&cdeg[__ldg(cluster + i)], 1);
}

__global__ __launch_bounds__(512) void scan_block(const int* __restrict__ in,
                                                  int* __restrict__ out,
                                                  int* __restrict__ sums, int n)
{
    __shared__ int s[512];
    int tid = threadIdx.x;
    int i = blockIdx.x * 512 + tid;
    int v = (i < n) ? in[i] : 0;
    s[tid] = v;
    __syncthreads();
#pragma unroll
    for (int off = 1; off < 512; off <<= 1) {
        int t = (tid >= off) ? s[tid - off] : 0;
        __syncthreads();
        s[tid] += t;
        __syncthreads();
    }
    if (i < n) out[i] = s[tid] - v;
    if (tid == 511) sums[blockIdx.x] = s[511];
}

__global__ __launch_bounds__(256) void scan_sums(int* __restrict__ sums, int nb)
{
    __shared__ int s[256];
    int tid = threadIdx.x;
    int v = (tid < nb) ? sums[tid] : 0;
    s[tid] = v;
    __syncthreads();
#pragma unroll
    for (int off = 1; off < 256; off <<= 1) {
        int t = (tid >= off) ? s[tid - off] : 0;
        __syncthreads();
        s[tid] += t;
        __syncthreads();
    }
    if (tid < nb) sums[tid] = s[tid] - v;
}

__global__ __launch_bounds__(512) void scan_add(int* __restrict__ out,
                                                const int* __restrict__ sums, int n)
{
    int i = blockIdx.x * 512 + threadIdx.x;
    if (i < n) out[i] += sums[blockIdx.x];
}

__global__ void scatter_edges(const int* __restrict__ ei, int E,
                              const int* __restrict__ rowptr, int* __restrict__ cursor,
                              int* __restrict__ esrc)
{
    int e = blockIdx.x * blockDim.x + threadIdx.x;
    if (e >= E) return;
    int src = __ldg(ei + e);
    int tgt = __ldg(ei + E + e);
    int pos = rowptr[tgt] + atomicAdd(&cursor[tgt], 1);
    esrc[pos] = src;
}

__global__ void scatter_nodes(const int* __restrict__ cluster, int n,
                              const int* __restrict__ cptr, int* __restrict__ ccur,
                              int* __restrict__ cnodes)
{
    int i = blockIdx.x * blockDim.x + threadIdx.x;
    if (i >= n) return;
    int cl = __ldg(cluster + i);
    int pos = cptr[cl] + atomicAdd(&ccur[cl], 1);
    cnodes[pos] = i;
}

// ---------------- GEMM1 (mma.sync bf16 split) + LN + ReLU -------------------
// H[N,64] = relu(LN(A[N,CIN] @ W1 + b1)*g + be); W passed as W1^T [64][CIN]
template<int CIN>
__global__ __launch_bounds__(256) void gemm1_ln(
    const __nv_bfloat16* __restrict__ Ahi, const __nv_bfloat16* __restrict__ Alo,
    const __nv_bfloat16* __restrict__ Whi, const __nv_bfloat16* __restrict__ Wlo,
    const float* __restrict__ b1, const float* __restrict__ gam,
    const float* __restrict__ bet,
    __nv_bfloat16* __restrict__ Hhi, __nv_bfloat16* __restrict__ Hlo, int n)
{
    constexpr int KT  = 64;
    constexpr int NKC = CIN / KT;
    constexpr int AS  = KT + 8;           // A smem row stride (elems)
    constexpr int WS  = CIN + 8;          // W smem row stride
    constexpr int A_ELEMS = 128 * AS;     // per split
    constexpr int W_ELEMS = 64 * WS;      // per split
    extern __shared__ __align__(16) __nv_bfloat16 sm[];
    __nv_bfloat16* Ash[2] = { sm, sm + A_ELEMS };
    __nv_bfloat16* Wsh[2] = { sm + 2 * A_ELEMS, sm + 2 * A_ELEMS + W_ELEMS };

    const int tid = threadIdx.x, wid = tid >> 5, lane = tid & 31;
    const int g = lane >> 2, q = lane & 3;
    const int r0 = blockIdx.x * 128;

    // load W^T [64][CIN] (hi, lo) into smem, once
    {
        constexpr int VPR = CIN / 8;          // 16B vectors per row
        for (int i = tid; i < 64 * VPR; i += 256) {
            int m = i / VPR, seg = i - m * VPR;
            *(uint4*)&Wsh[0][m * WS + seg * 8] = __ldg((const uint4*)(Whi + (size_t)m * CIN) + seg);
            *(uint4*)&Wsh[1][m * WS + seg * 8] = __ldg((const uint4*)(Wlo + (size_t)m * CIN) + seg);
        }
    }

    float acc[8][4] = {};

    for (int kc = 0; kc < NKC; kc++) {
        __syncthreads();
        // stage A chunk [128][64] (hi, lo)
        for (int i = tid; i < 128 * 8; i += 256) {
            int m = i >> 3, seg = i & 7;
            int r = r0 + m;
            uint4 vh = make_uint4(0,0,0,0), vl = vh;
            if (r < n) {
                vh = __ldg((const uint4*)(Ahi + (size_t)r * CIN + kc * KT) + seg);
                vl = __ldg((const uint4*)(Alo + (size_t)r * CIN + kc * KT) + seg);
            }
            *(uint4*)&Ash[0][m * AS + seg * 8] = vh;
            *(uint4*)&Ash[1][m * AS + seg * 8] = vl;
        }
        __syncthreads();

        const __nv_bfloat16* A0 = Ash[0] + (wid * 16) * AS;
        const __nv_bfloat16* A1 = Ash[1] + (wid * 16) * AS;
#pragma unroll
        for (int ks = 0; ks < 4; ks++) {
            int k0 = ks * 16;
            uint32_t ah0 = *(const uint32_t*)&A0[(g    ) * AS + k0 + 2*q];
            uint32_t ah1 = *(const uint32_t*)&A0[(g + 8) * AS + k0 + 2*q];
            uint32_t ah2 = *(const uint32_t*)&A0[(g    ) * AS + k0 + 2*q + 8];
            uint32_t ah3 = *(const uint32_t*)&A0[(g + 8) * AS + k0 + 2*q + 8];
            uint32_t al0 = *(const uint32_t*)&A1[(g    ) * AS + k0 + 2*q];
            uint32_t al1 = *(const uint32_t*)&A1[(g + 8) * AS + k0 + 2*q];
            uint32_t al2 = *(const uint32_t*)&A1[(g    ) * AS + k0 + 2*q + 8];
            uint32_t al3 = *(const uint32_t*)&A1[(g + 8) * AS + k0 + 2*q + 8];
            int kg = kc * KT + k0;
#pragma unroll
            for (int j = 0; j < 8; j++) {
                const __nv_bfloat16* w0 = Wsh[0] + (8*j + g) * WS + kg + 2*q;
                const __nv_bfloat16* w1 = Wsh[1] + (8*j + g) * WS + kg + 2*q;
                uint32_t bh0 = *(const uint32_t*)(w0);
                uint32_t bh1 = *(const uint32_t*)(w0 + 8);
                uint32_t bl0 = *(const uint32_t*)(w1);
                uint32_t bl1 = *(const uint32_t*)(w1 + 8);
                mma16816(acc[j], ah0, ah1, ah2, ah3, bh0, bh1);   // hi*hi
                mma16816(acc[j], ah0, ah1, ah2, ah3, bl0, bl1);   // hi*lo
                mma16816(acc[j], al0, al1, al2, al3, bh0, bh1);   // lo*hi
            }
        }
    }

    // ---- epilogue: bias + LayerNorm (quad shuffle) + ReLU + split store ----
    float v0[16], v1[16];
    float s0 = 0.f, q0 = 0.f, s1 = 0.f, q1 = 0.f;
#pragma unroll
    for (int j = 0; j < 8; j++) {
        int c0 = 8*j + 2*q;
        float bx = __ldg(b1 + c0), by = __ldg(b1 + c0 + 1);
        float a = acc[j][0] + bx, b = acc[j][1] + by;
        float c = acc[j][2] + bx, d = acc[j][3] + by;
        v0[2*j] = a; v0[2*j+1] = b; v1[2*j] = c; v1[2*j+1] = d;
        s0 += a + b; q0 += a*a + b*b;
        s1 += c + d; q1 += c*c + d*d;
    }
#pragma unroll
    for (int off = 1; off < 4; off <<= 1) {
        s0 += __shfl_xor_sync(0xffffffffu, s0, off);
        q0 += __shfl_xor_sync(0xffffffffu, q0, off);
        s1 += __shfl_xor_sync(0xffffffffu, s1, off);
        q1 += __shfl_xor_sync(0xffffffffu, q1, off);
    }
    float mu0 = s0 * (1.f/64.f), var0 = q0 * (1.f/64.f) - mu0*mu0;
    float mu1 = s1 * (1.f/64.f), var1 = q1 * (1.f/64.f) - mu1*mu1;
    float rs0 = rsqrtf(var0 + LN_EPS), rs1 = rsqrtf(var1 + LN_EPS);

    int rg0 = r0 + wid * 16 + g;
    int rg1 = rg0 + 8;
    if (rg0 < n) {
        uint32_t* oh = (uint32_t*)(Hhi + (size_t)rg0 * 64);
        uint32_t* ol = (uint32_t*)(Hlo + (size_t)rg0 * 64);
#pragma unroll
        for (int j = 0; j < 8; j++) {
            int c0 = 8*j + 2*q;
            float f0 = fmaxf((v0[2*j]   - mu0) * rs0 * __ldg(gam + c0)     + __ldg(bet + c0),     0.f);
            float f1 = fmaxf((v0[2*j+1] - mu0) * rs0 * __ldg(gam + c0 + 1) + __ldg(bet + c0 + 1), 0.f);
            uint32_t h, l; split2(f0, f1, h, l);
            oh[c0 >> 1] = h; ol[c0 >> 1] = l;
        }
    }
    if (rg1 < n) {
        uint32_t* oh = (uint32_t*)(Hhi + (size_t)rg1 * 64);
        uint32_t* ol = (uint32_t*)(Hlo + (size_t)rg1 * 64);
#pragma unroll
        for (int j = 0; j < 8; j++) {
            int c0 = 8*j + 2*q;
            float f0 = fmaxf((v1[2*j]   - mu1) * rs1 * __ldg(gam + c0)     + __ldg(bet + c0),     0.f);
            float f1 = fmaxf((v1[2*j+1] - mu1) * rs1 * __ldg(gam + c0 + 1) + __ldg(bet + c0 + 1), 0.f);
            uint32_t h, l; split2(f0, f1, h, l);
            oh[c0 >> 1] = h; ol[c0 >> 1] = l;
        }
    }
}

// ---------------- GEMM2 (mma.sync bf16 split) + bias -> split concat half ---
// Y[:,0:COUT] = H[N,64] @ W2 + b2; W passed as W2^T [COUT][64]; row stride 2*COUT
template<int COUT>
__global__ __launch_bounds__(256) void gemm2_k(
    const __nv_bfloat16* __restrict__ Ahi, const __nv_bfloat16* __restrict__ Alo,
    const __nv_bfloat16* __restrict__ Whi, const __nv_bfloat16* __restrict__ Wlo,
    const float* __restrict__ b2,
    __nv_bfloat16* __restrict__ Yhi, __nv_bfloat16* __restrict__ Ylo, int n)
{
    constexpr int AS = 72;                 // 64 + 8
    constexpr int A_ELEMS = 128 * AS;
    constexpr int W_ELEMS = COUT * AS;
    constexpr int NG = COUT / 64;
    extern __shared__ __align__(16) __nv_bfloat16 sm[];
    __nv_bfloat16* Ash[2] = { sm, sm + A_ELEMS };
    __nv_bfloat16* Wsh[2] = { sm + 2 * A_ELEMS, sm + 2 * A_ELEMS + W_ELEMS };

    const int tid = threadIdx.x, wid = tid >> 5, lane = tid & 31;
    const int g = lane >> 2, q = lane & 3;
    const int r0 = blockIdx.x * 128;

    for (int i = tid; i < COUT * 8; i += 256) {
        int m = i >> 3, seg = i & 7;
        *(uint4*)&Wsh[0][m * AS + seg * 8] = __ldg((const uint4*)(Whi + (size_t)m * 64) + seg);
        *(uint4*)&Wsh[1][m * AS + seg * 8] = __ldg((const uint4*)(Wlo + (size_t)m * 64) + seg);
    }
    for (int i = tid; i < 128 * 8; i += 256) {
        int m = i >> 3, seg = i & 7;
        int r = r0 + m;
        uint4 vh = make_uint4(0,0,0,0), vl = vh;
        if (r < n) {
            vh = __ldg((const uint4*)(Ahi + (size_t)r * 64) + seg);
            vl = __ldg((const uint4*)(Alo + (size_t)r * 64) + seg);
        }
        *(uint4*)&Ash[0][m * AS + seg * 8] = vh;
        *(uint4*)&Ash[1][m * AS + seg * 8] = vl;
    }
    __syncthreads();

    const __nv_bfloat16* A0 = Ash[0] + (wid * 16) * AS;
    const __nv_bfloat16* A1 = Ash[1] + (wid * 16) * AS;
    const int rg0 = r0 + wid * 16 + g;
    const int rg1 = rg0 + 8;

#pragma unroll
    for (int ng = 0; ng < NG; ng++) {
        float acc[8][4] = {};
#pragma unroll
        for (int ks = 0; ks < 4; ks++) {
            int k0 = ks * 16;
            uint32_t ah0 = *(const uint32_t*)&A0[(g    ) * AS + k0 + 2*q];
            uint32_t ah1 = *(const uint32_t*)&A0[(g + 8) * AS + k0 + 2*q];
            uint32_t ah2 = *(const uint32_t*)&A0[(g    ) * AS + k0 + 2*q + 8];
            uint32_t ah3 = *(const uint32_t*)&A0[(g + 8) * AS + k0 + 2*q + 8];
            uint32_t al0 = *(const uint32_t*)&A1[(g    ) * AS + k0 + 2*q];
            uint32_t al1 = *(const uint32_t*)&A1[(g + 8) * AS + k0 + 2*q];
            uint32_t al2 = *(const uint32_t*)&A1[(g    ) * AS + k0 + 2*q + 8];
            uint32_t al3 = *(const uint32_t*)&A1[(g + 8) * AS + k0 + 2*q + 8];
#pragma unroll
            for (int j = 0; j < 8; j++) {
                const __nv_bfloat16* w0 = Wsh[0] + (ng*64 + 8*j + g) * AS + k0 + 2*q;
                const __nv_bfloat16* w1 = Wsh[1] + (ng*64 + 8*j + g) * AS + k0 + 2*q;
                uint32_t bh0 = *(const uint32_t*)(w0);
                uint32_t bh1 = *(const uint32_t*)(w0 + 8);
                uint32_t bl0 = *(const uint32_t*)(w1);
                uint32_t bl1 = *(const uint32_t*)(w1 + 8);
                mma16816(acc[j], ah0, ah1, ah2, ah3, bh0, bh1);
                mma16816(acc[j], ah0, ah1, ah2, ah3, bl0, bl1);
                mma16816(acc[j], al0, al1, al2, al3, bh0, bh1);
            }
        }
        if (rg0 < n) {
            uint32_t* oh = (uint32_t*)(Yhi + (size_t)rg0 * (2*COUT) + ng*64);
            uint32_t* ol = (uint32_t*)(Ylo + (size_t)rg0 * (2*COUT) + ng*64);
#pragma unroll
            for (int j = 0; j < 8; j++) {
                int c0 = 8*j + 2*q;
                float f0 = acc[j][0] + __ldg(b2 + ng*64 + c0);
                float f1 = acc[j][1] + __ldg(b2 + ng*64 + c0 + 1);
                uint32_t h, l; split2(f0, f1, h, l);
                oh[c0 >> 1] = h; ol[c0 >> 1] = l;
            }
        }
        if (rg1 < n) {
            uint32_t* oh = (uint32_t*)(Yhi + (size_t)rg1 * (2*COUT) + ng*64);
            uint32_t* ol = (uint32_t*)(Ylo + (size_t)rg1 * (2*COUT) + ng*64);
#pragma unroll
            for (int j = 0; j < 8; j++) {
                int c0 = 8*j + 2*q;
                float f0 = acc[j][2] + __ldg(b2 + ng*64 + c0);
                float f1 = acc[j][3] + __ldg(b2 + ng*64 + c0 + 1);
                uint32_t h, l; split2(f0, f1, h, l);
                oh[c0 >> 1] = h; ol[c0 >> 1] = l;
            }
        }
    }
}

// ---------------- CSR gather-max aggregation (split bf16) --------------------
template<int C>
__global__ __launch_bounds__(256) void agg_bf16(
    __nv_bfloat16* __restrict__ Yhi, __nv_bfloat16* __restrict__ Ylo,
    const int* __restrict__ rowptr, const int* __restrict__ deg,
    const int* __restrict__ esrc, int n)
{
    int w = (blockIdx.x * blockDim.x + threadIdx.x) >> 5;
    if (w >= n) return;
    const int lane = threadIdx.x & 31;
    constexpr int FP = C / 64;               // bf16x2 words per lane
    float mx[2 * FP];
#pragma unroll
    for (int i = 0; i < 2 * FP; i++) mx[i] = neg_inf();
    int d = __ldg(deg + w), base = __ldg(rowptr + w);
    for (int j = 0; j < d; j++) {
        int src = __ldg(esrc + base + j);
        const uint32_t* rh = (const uint32_t*)(Yhi + (size_t)src * (2 * C));
        const uint32_t* rl = (const uint32_t*)(Ylo + (size_t)src * (2 * C));
#pragma unroll
        for (int i = 0; i < FP; i++) {
            uint32_t uh = __ldg(rh + lane + i * 32);
            uint32_t ul = __ldg(rl + lane + i * 32);
            float2 fh = __bfloat1622float2(*(__nv_bfloat162*)&uh);
            float2 fl = __bfloat1622float2(*(__nv_bfloat162*)&ul);
            mx[2*i]   = fmaxf(mx[2*i],   fh.x + fl.x);
            mx[2*i+1] = fmaxf(mx[2*i+1], fh.y + fl.y);
        }
    }
    uint32_t* oh = (uint32_t*)(Yhi + (size_t)w * (2 * C) + C);
    uint32_t* ol = (uint32_t*)(Ylo + (size_t)w * (2 * C) + C);
#pragma unroll
    for (int i = 0; i < FP; i++) {
        uint32_t h = 0, l = 0;
        if (d) split2(mx[2*i], mx[2*i+1], h, l);
        oh[lane + i * 32] = h;
        ol[lane + i * 32] = l;
    }
}

// ---------------- CSR cluster max-pool (split bf16 in, fp32 out) ------------
__global__ __launch_bounds__(128) void pool_bf16(
    const __nv_bfloat16* __restrict__ Yhi, const __nv_bfloat16* __restrict__ Ylo,
    const int* __restrict__ cptr, const int* __restrict__ cdeg,
    const int* __restrict__ cnodes, float* __restrict__ out)
{
    int cl = blockIdx.x, t = threadIdx.x;
    int d = __ldg(cdeg + cl), base = __ldg(cptr + cl);
    float m0 = neg_inf(), m1 = neg_inf(), m2 = neg_inf(), m3 = neg_inf();
    for (int j = 0; j < d; j++) {
        int nd = __ldg(cnodes + base + j);
        const uint32_t* rh = (const uint32_t*)(Yhi + (size_t)nd * 512);
        const uint32_t* rl = (const uint32_t*)(Ylo + (size_t)nd * 512);
        uint32_t h0 = __ldg(rh + t),       l0 = __ldg(rl + t);
        uint32_t h1 = __ldg(rh + t + 128), l1 = __ldg(rl + t + 128);
        float2 a = __bfloat1622float2(*(__nv_bfloat162*)&h0);
        float2 b = __bfloat1622float2(*(__nv_bfloat162*)&l0);
        float2 c = __bfloat1622float2(*(__nv_bfloat162*)&h1);
        float2 e = __bfloat1622float2(*(__nv_bfloat162*)&l1);
        m0 = fmaxf(m0, a.x + b.x); m1 = fmaxf(m1, a.y + b.y);
        m2 = fmaxf(m2, c.x + e.x); m3 = fmaxf(m3, c.y + e.y);
    }
    if (!d) { m0 = m1 = m2 = m3 = 0.f; }
    out[(size_t)cl * 512 + 2 * t]           = m0;
    out[(size_t)cl * 512 + 2 * t + 1]       = m1;
    out[(size_t)cl * 512 + 256 + 2 * t]     = m2;
    out[(size_t)cl * 512 + 256 + 2 * t + 1] = m3;
}

// ---------------- column L2 normalize ---------------------------------------
__global__ __launch_bounds__(512) void colsq_kernel(const float* __restrict__ out,
                                                    float* __restrict__ colsq, int nc)
{
    const int ROWS = 50;
    int c  = threadIdx.x;
    int r0 = blockIdx.x * ROWS;
    int r1 = min(r0 + ROWS, nc);
    float s = 0.f;
    for (int r = r0; r < r1; r++) {
        float f = out[(size_t)r * 512 + c];
        s += f * f;
    }
    atomicAdd(colsq + c, s);
}

__global__ void scale_kernel(float* __restrict__ out, const float* __restrict__ colsq, int nc)
{
    int gid = blockIdx.x * blockDim.x + threadIdx.x;
    if (gid >= nc * 512) return;
    int c = gid & 511;
    out[gid] = out[gid] / sqrtf(__ldg(colsq + c));
}

// ---------------- launch ----------------------------------------------------
extern "C" void kernel_launch(void* const* d_in, const int* in_sizes, int n_in,
                              void* d_out, int out_size)
{
    const float* x       = (const float*)d_in[0];
    const int*   ei      = (const int*)d_in[1];
    const int*   cluster = (const int*)d_in[2];
    const int N  = in_sizes[0] / 64;
    const int E  = in_sizes[1] / 2;
    const int NC = out_size / 512;
    float* out = (float*)d_out;

    __nv_bfloat16 *xhi, *xlo, *hhi, *hlo;
    __nv_bfloat16 *y0hi, *y0lo, *y1hi, *y1lo, *y2hi, *y2lo;
    __nv_bfloat16 *w1h[3], *w1l[3], *w2h[3], *w2l[3];
    float *colsq;
    int *deg, *rowptr, *cursor, *esrc, *cdeg, *cptr, *ccur, *cnodes, *bsumsN, *bsumsC;
    cudaGetSymbolAddress((void**)&xhi,  g_xhi);   cudaGetSymbolAddress((void**)&xlo,  g_xlo);
    cudaGetSymbolAddress((void**)&hhi,  g_hhi);   cudaGetSymbolAddress((void**)&hlo,  g_hlo);
    cudaGetSymbolAddress((void**)&y0hi, g_y0hi);  cudaGetSymbolAddress((void**)&y0lo, g_y0lo);
    cudaGetSymbolAddress((void**)&y1hi, g_y1hi);  cudaGetSymbolAddress((void**)&y1lo, g_y1lo);
    cudaGetSymbolAddress((void**)&y2hi, g_y2hi);  cudaGetSymbolAddress((void**)&y2lo, g_y2lo);
    cudaGetSymbolAddress((void**)&w1h[0], g_w1thi0); cudaGetSymbolAddress((void**)&w1l[0], g_w1tlo0);
    cudaGetSymbolAddress((void**)&w1h[1], g_w1thi1); cudaGetSymbolAddress((void**)&w1l[1], g_w1tlo1);
    cudaGetSymbolAddress((void**)&w1h[2], g_w1thi2); cudaGetSymbolAddress((void**)&w1l[2], g_w1tlo2);
    cudaGetSymbolAddress((void**)&w2h[0], g_w2thi0); cudaGetSymbolAddress((void**)&w2l[0], g_w2tlo0);
    cudaGetSymbolAddress((void**)&w2h[1], g_w2thi1); cudaGetSymbolAddress((void**)&w2l[1], g_w2tlo1);
    cudaGetSymbolAddress((void**)&w2h[2], g_w2thi2); cudaGetSymbolAddress((void**)&w2l[2], g_w2tlo2);
    cudaGetSymbolAddress((void**)&colsq,  g_colsq);
    cudaGetSymbolAddress((void**)&deg,    g_deg);
    cudaGetSymbolAddress((void**)&rowptr, g_rowptr);
    cudaGetSymbolAddress((void**)&cursor, g_cursor);
    cudaGetSymbolAddress((void**)&esrc,   g_esrc);
    cudaGetSymbolAddress((void**)&cdeg,   g_cdeg);
    cudaGetSymbolAddress((void**)&cptr,   g_cptr);
    cudaGetSymbolAddress((void**)&ccur,   g_ccur);
    cudaGetSymbolAddress((void**)&cnodes, g_cnodes);
    cudaGetSymbolAddress((void**)&bsumsN, g_bsumsN);
    cudaGetSymbolAddress((void**)&bsumsC, g_bsumsC);

    // dynamic smem sizes (bytes): 2*(128*AS + rows*WS)*2 per kernel
    const int G1S[3] = { 55296, 71680, 104448 };   // CIN = 64,128,256
    const int G2S[3] = { 55296, 73728, 110592 };   // COUT = 64,128,256
    cudaFuncSetAttribute(gemm1_ln<64>,  cudaFuncAttributeMaxDynamicSharedMemorySize, G1S[0]);
    cudaFuncSetAttribute(gemm1_ln<128>, cudaFuncAttributeMaxDynamicSharedMemorySize, G1S[1]);
    cudaFuncSetAttribute(gemm1_ln<256>, cudaFuncAttributeMaxDynamicSharedMemorySize, G1S[2]);
    cudaFuncSetAttribute(gemm2_k<64>,   cudaFuncAttributeMaxDynamicSharedMemorySize, G2S[0]);
    cudaFuncSetAttribute(gemm2_k<128>,  cudaFuncAttributeMaxDynamicSharedMemorySize, G2S[1]);
    cudaFuncSetAttribute(gemm2_k<256>,  cudaFuncAttributeMaxDynamicSharedMemorySize, G2S[2]);

    const int GRID = (N + 127) / 128;
    const int nbN = (N + 511) / 512;
    const int nbC = (NC + 511) / 512;

    // ---- CSR build ----
    cudaMemsetAsync(deg,    0, N  * sizeof(int));
    cudaMemsetAsync(cursor, 0, N  * sizeof(int));
    cudaMemsetAsync(cdeg,   0, NC * sizeof(int));
    cudaMemsetAsync(ccur,   0, NC * sizeof(int));
    hist_edges<<<(E + 255) / 256, 256>>>(ei, E, deg);
    hist_nodes<<<(N + 255) / 256, 256>>>(cluster, N, cdeg);
    scan_block<<<nbN, 512>>>(deg, rowptr, bsumsN, N);
    scan_sums<<<1, 256>>>(bsumsN, nbN);
    scan_add<<<nbN, 512>>>(rowptr, bsumsN, N);
    scan_block<<<nbC, 512>>>(cdeg, cptr, bsumsC, NC);
    scan_sums<<<1, 256>>>(bsumsC, nbC);
    scan_add<<<nbC, 512>>>(cptr, bsumsC, NC);
    scatter_edges<<<(E + 255) / 256, 256>>>(ei, E, rowptr, cursor, esrc);
    scatter_nodes<<<(N + 255) / 256, 256>>>(cluster, N, cptr, ccur, cnodes);

    // ---- conversions (fp32 -> split bf16; weights transposed) ----
    conv_split<<<(N * 64 + 255) / 256, 256>>>(x, xhi, xlo, N * 64);
    const int CINs[3] = {64, 128, 256};
    for (int i = 0; i < 3; i++) {
        const float* W1 = (const float*)d_in[3 + 6 * i];
        const float* W2 = (const float*)d_in[3 + 6 * i + 4];
        int c = CINs[i];
        conv_split_T<<<(c * 64 + 255) / 256, 256>>>(W1, w1h[i], w1l[i], c, 64);   // [c,64]->[64,c]
        conv_split_T<<<(64 * c + 255) / 256, 256>>>(W2, w2h[i], w2l[i], 64, c);   // [64,c]->[c,64]
    }

    // ---- layer 0: CIN=64 ----
    {
        const float* b1 = (const float*)d_in[4];
        const float* g  = (const float*)d_in[5];
        const float* be = (const float*)d_in[6];
        const float* b2 = (const float*)d_in[8];
        gemm1_ln<64><<<GRID, 256, G1S[0]>>>(xhi, xlo, w1h[0], w1l[0], b1, g, be, hhi, hlo, N);
        gemm2_k<64><<<GRID, 256, G2S[0]>>>(hhi, hlo, w2h[0], w2l[0], b2, y0hi, y0lo, N);
        agg_bf16<64><<<(N + 7) / 8, 256>>>(y0hi, y0lo, rowptr, deg, esrc, N);
    }
    // ---- layer 1: CIN=128 ----
    {
        const float* b1 = (const float*)d_in[10];
        const float* g  = (const float*)d_in[11];
        const float* be = (const float*)d_in[12];
        const float* b2 = (const float*)d_in[14];
        gemm1_ln<128><<<GRID, 256, G1S[1]>>>(y0hi, y0lo, w1h[1], w1l[1], b1, g, be, hhi, hlo, N);
        gemm2_k<128><<<GRID, 256, G2S[1]>>>(hhi, hlo, w2h[1], w2l[1], b2, y1hi, y1lo, N);
        agg_bf16<128><<<(N + 7) / 8, 256>>>(y1hi, y1lo, rowptr, deg, esrc, N);
    }
    // ---- layer 2: CIN=256 ----
    {
        const float* b1 = (const float*)d_in[16];
        const float* g  = (const float*)d_in[17];
        const float* be = (const float*)d_in[18];
        const float* b2 = (const float*)d_in[20];
        gemm1_ln<256><<<GRID, 256, G1S[2]>>>(y1hi, y1lo, w1h[2], w1l[2], b1, g, be, hhi, hlo, N);
        gemm2_k<256><<<GRID, 256, G2S[2]>>>(hhi, hlo, w2h[2], w2l[2], b2, y2hi, y2lo, N);
        agg_bf16<256><<<(N + 7) / 8, 256>>>(y2hi, y2lo, rowptr, deg, esrc, N);
    }
    // ---- cluster max-pool + column L2 normalize ----
    pool_bf16<<<NC, 128>>>(y2hi, y2lo, cptr, cdeg, cnodes, out);
    cudaMemsetAsync(colsq, 0, 512 * sizeof(float));
    colsq_kernel<<<(NC + 49) / 50, 512>>>(out, colsq, NC);
    scale_kernel<<<(NC * 512 + 255) / 256, 256>>>(out, colsq, NC);
}

// round 7
// speedup vs baseline: 3.3775x; 1.1183x over previous
#include <cuda_runtime.h>
#include <cuda_bf16.h>
#include <cstdint>

#define LN_EPS 1e-5f

// ---------------- scratch (device globals: allocation-free) ----------------
// y buffers: interleaved split rows; entry j = uint2{ bf16x2 hi, bf16x2 lo } for
// channels (2j, 2j+1). Row entries = 2*COUT/2 = COUT (first half GEMM, second agg).
__device__ __align__(128) uint2 g_y0[100000 * 64];    // layer0 out (128 ch)
__device__ __align__(128) uint2 g_y1[100000 * 128];   // layer1 out (256 ch)
__device__ __align__(128) uint2 g_y2[100000 * 256];   // layer2 out (512 ch)
__device__ __align__(128) __nv_bfloat16 g_w1thi0[64*64],  g_w1tlo0[64*64];
__device__ __align__(128) __nv_bfloat16 g_w1thi1[64*128], g_w1tlo1[64*128];
__device__ __align__(128) __nv_bfloat16 g_w1thi2[64*256], g_w1tlo2[64*256];
__device__ __align__(128) __nv_bfloat16 g_w2thi0[64*64],  g_w2tlo0[64*64];
__device__ __align__(128) __nv_bfloat16 g_w2thi1[128*64], g_w2tlo1[128*64];
__device__ __align__(128) __nv_bfloat16 g_w2thi2[256*64], g_w2tlo2[256*64];
__device__ float g_colsq[512];

// CSR scratch
__device__ int g_deg[100000];
__device__ int g_rowptr[100000];
__device__ int g_cursor[100000];
__device__ int g_esrc[800000];
__device__ int g_cdeg[10000];
__device__ int g_cptr[10000];
__device__ int g_ccur[10000];
__device__ int g_cnodes[100000];
__device__ int g_bsumsN[512];
__device__ int g_bsumsC[512];

__device__ __forceinline__ float neg_inf() { return __int_as_float(0xff800000); }

// fp32 pair -> (bf16 hi, bf16 lo) packed words (low half = first value)
__device__ __forceinline__ void split2(float a, float b, uint32_t& hi, uint32_t& lo) {
    __nv_bfloat16 ah = __float2bfloat16_rn(a);
    __nv_bfloat16 bh = __float2bfloat16_rn(b);
    __nv_bfloat16 al = __float2bfloat16_rn(a - __bfloat162float(ah));
    __nv_bfloat16 bl = __float2bfloat16_rn(b - __bfloat162float(bh));
    __nv_bfloat162 h = __halves2bfloat162(ah, bh);
    __nv_bfloat162 l = __halves2bfloat162(al, bl);
    hi = *reinterpret_cast<uint32_t*>(&h);
    lo = *reinterpret_cast<uint32_t*>(&l);
}

__device__ __forceinline__ void mma16816(float* c, uint32_t a0, uint32_t a1,
                                         uint32_t a2, uint32_t a3,
                                         uint32_t b0, uint32_t b1) {
    asm volatile(
        "mma.sync.aligned.m16n8k16.row.col.f32.bf16.bf16.f32 "
        "{%0,%1,%2,%3}, {%4,%5,%6,%7}, {%8,%9}, {%0,%1,%2,%3};"
        : "+f"(c[0]), "+f"(c[1]), "+f"(c[2]), "+f"(c[3])
        : "r"(a0), "r"(a1), "r"(a2), "r"(a3), "r"(b0), "r"(b1));
}

// ---------------- fused weight conversion (all 6 tensors, transposed) -------
struct WConv {
    const float* in[6];
    __nv_bfloat16* hi[6];
    __nv_bfloat16* lo[6];
    int K[6], M[6];
    int off[7];
};

__global__ void conv_weights(WConv a)
{
    int gid = blockIdx.x * blockDim.x + threadIdx.x;
    if (gid >= a.off[6]) return;
    int s = 0;
#pragma unroll
    for (int i = 1; i < 6; i++) if (gid >= a.off[i]) s = i;
    int local = gid - a.off[s];
    int M = a.M[s], K = a.K[s];
    int k = local / M, m = local - k * M;
    float v = __ldg(a.in[s] + local);
    __nv_bfloat16 h = __float2bfloat16_rn(v);
    a.hi[s][m * K + k] = h;
    a.lo[s][m * K + k] = __float2bfloat16_rn(v - __bfloat162float(h));
}

// ---------------- CSR build (fused) -----------------------------------------
__global__ void zero_all(int* __restrict__ deg, int* __restrict__ cursor,
                         int* __restrict__ cdeg, int* __restrict__ ccur,
                         float* __restrict__ colsq, int n, int nc)
{
    int i = blockIdx.x * blockDim.x + threadIdx.x;
    if (i < n) { deg[i] = 0; cursor[i] = 0; }
    if (i < nc) { cdeg[i] = 0; ccur[i] = 0; }
    if (i < 512) colsq[i] = 0.f;
}

__global__ void hist_fused(const int* __restrict__ ei, int E,
                           const int* __restrict__ cluster, int n,
                           int* __restrict__ deg, int* __restrict__ cdeg)
{
    int gid = blockIdx.x * blockDim.x + threadIdx.x;
    if (gid < E) {
        atomicAdd(&deg[__ldg(ei + E + gid)], 1);
    } else if (gid < E + n) {
        atomicAdd(&cdeg[__ldg(cluster + gid - E)], 1);
    }
}

__global__ __launch_bounds__(512) void scan_block2(
    const int* __restrict__ inN, int* __restrict__ outN, int* __restrict__ sumsN, int n, int nbN,
    const int* __restrict__ inC, int* __restrict__ outC, int* __restrict__ sumsC, int nc)
{
    __shared__ int s[512];
    int tid = threadIdx.x;
    const int* in;  int* out; int* sums; int len; int blk;
    if ((int)blockIdx.x < nbN) { in = inN; out = outN; sums = sumsN; len = n;  blk = blockIdx.x; }
    else                       { in = inC; out = outC; sums = sumsC; len = nc; blk = blockIdx.x - nbN; }
    int i = blk * 512 + tid;
    int v = (i < len) ? in[i] : 0;
    s[tid] = v;
    __syncthreads();
#pragma unroll
    for (int off = 1; off < 512; off <<= 1) {
        int t = (tid >= off) ? s[tid - off] : 0;
        __syncthreads();
        s[tid] += t;
        __syncthreads();
    }
    if (i < len) out[i] = s[tid] - v;
    if (tid == 511) sums[blk] = s[511];
}

__global__ __launch_bounds__(256) void scan_sums2(int* __restrict__ sumsN, int nbN,
                                                  int* __restrict__ sumsC, int nbC)
{
    __shared__ int s[256];
    int tid = threadIdx.x;
    int* sums = blockIdx.x == 0 ? sumsN : sumsC;
    int nb    = blockIdx.x == 0 ? nbN   : nbC;
    int v = (tid < nb) ? sums[tid] : 0;
    s[tid] = v;
    __syncthreads();
#pragma unroll
    for (int off = 1; off < 256; off <<= 1) {
        int t = (tid >= off) ? s[tid - off] : 0;
        __syncthreads();
        s[tid] += t;
        __syncthreads();
    }
    if (tid < nb) sums[tid] = s[tid] - v;
}

__global__ __launch_bounds__(512) void scan_add2(
    int* __restrict__ outN, const int* __restrict__ sumsN, int n, int nbN,
    int* __restrict__ outC, const int* __restrict__ sumsC, int nc)
{
    int tid = threadIdx.x;
    if ((int)blockIdx.x < nbN) {
        int i = blockIdx.x * 512 + tid;
        if (i < n) outN[i] += sumsN[blockIdx.x];
    } else {
        int blk = blockIdx.x - nbN;
        int i = blk * 512 + tid;
        if (i < nc) outC[i] += sumsC[blk];
    }
}

__global__ void scatter_fused(const int* __restrict__ ei, int E,
                              const int* __restrict__ cluster, int n,
                              const int* __restrict__ rowptr, int* __restrict__ cursor,
                              int* __restrict__ esrc,
                              const int* __restrict__ cptr, int* __restrict__ ccur,
                              int* __restrict__ cnodes)
{
    int gid = blockIdx.x * blockDim.x + threadIdx.x;
    if (gid < E) {
        int src = __ldg(ei + gid);
        int tgt = __ldg(ei + E + gid);
        int pos = rowptr[tgt] + atomicAdd(&cursor[tgt], 1);
        esrc[pos] = src;
    } else if (gid < E + n) {
        int i = gid - E;
        int cl = __ldg(cluster + i);
        int pos = cptr[cl] + atomicAdd(&ccur[cl], 1);
        cnodes[pos] = i;
    }
}

// ---------------- fused MLP layer: gemm1+bias+LN+ReLU+gemm2+bias ------------
// A[N,C] (fp32 if F32 else interleaved-split uint2, C/2 entries/row)
// W1T [64][C] split, W2T [C][64] split; out: y interleaved, row C uint2 entries
template<int C, bool F32>
__global__ __launch_bounds__(256) void fused_mlp(
    const void* __restrict__ Ain,
    const __nv_bfloat16* __restrict__ W1hi, const __nv_bfloat16* __restrict__ W1lo,
    const float* __restrict__ b1, const float* __restrict__ gam,
    const float* __restrict__ bet,
    const __nv_bfloat16* __restrict__ W2hi, const __nv_bfloat16* __restrict__ W2lo,
    const float* __restrict__ b2,
    uint2* __restrict__ Y, int n)
{
    constexpr int AS  = 72;              // A/H smem row stride (elems)
    constexpr int WS  = C + 8;           // W1 smem row stride
    constexpr int NKC = C / 64;
    constexpr int NG  = C / 64;
    constexpr int W1E = 64 * WS;         // per split
    constexpr int AE  = 128 * AS;
    constexpr int W2E = C * AS;
    extern __shared__ __align__(16) __nv_bfloat16 sm[];
    __nv_bfloat16* W1s[2] = { sm, sm + W1E };
    __nv_bfloat16* As[2]  = { sm + 2 * W1E, sm + 2 * W1E + AE };          // reused as H
    __nv_bfloat16* W2s[2] = { sm + 2 * W1E + 2 * AE, sm + 2 * W1E + 2 * AE + W2E };

    const int tid = threadIdx.x, wid = tid >> 5, lane = tid & 31;
    const int g = lane >> 2, q = lane & 3;
    const int r0 = blockIdx.x * 128;

    // load weights
    {
        constexpr int VPR = C / 8;
        for (int i = tid; i < 64 * VPR; i += 256) {
            int m = i / VPR, seg = i - m * VPR;
            *(uint4*)&W1s[0][m * WS + seg * 8] = __ldg((const uint4*)(W1hi + (size_t)m * C) + seg);
            *(uint4*)&W1s[1][m * WS + seg * 8] = __ldg((const uint4*)(W1lo + (size_t)m * C) + seg);
        }
        for (int i = tid; i < C * 8; i += 256) {
            int m = i >> 3, seg = i & 7;
            *(uint4*)&W2s[0][m * AS + seg * 8] = __ldg((const uint4*)(W2hi + (size_t)m * 64) + seg);
            *(uint4*)&W2s[1][m * AS + seg * 8] = __ldg((const uint4*)(W2lo + (size_t)m * 64) + seg);
        }
    }

    float acc[8][4] = {};

    for (int kc = 0; kc < NKC; kc++) {
        __syncthreads();
        // stage A chunk [128][64]
        for (int i = tid; i < 128 * 32; i += 256) {
            int m = i >> 5, e = i & 31;
            int r = r0 + m;
            uint32_t h = 0, l = 0;
            if (r < n) {
                if (F32) {
                    float2 v = __ldg((const float2*)Ain + (size_t)r * (C / 2) + kc * 32 + e);
                    split2(v.x, v.y, h, l);
                } else {
                    uint2 v = __ldg((const uint2*)Ain + (size_t)r * (C / 2) + kc * 32 + e);
                    h = v.x; l = v.y;
                }
            }
            *(uint32_t*)&As[0][m * AS + 2 * e] = h;
            *(uint32_t*)&As[1][m * AS + 2 * e] = l;
        }
        __syncthreads();

        const __nv_bfloat16* A0 = As[0] + (wid * 16) * AS;
        const __nv_bfloat16* A1 = As[1] + (wid * 16) * AS;
#pragma unroll
        for (int ks = 0; ks < 4; ks++) {
            int k0 = ks * 16;
            uint32_t ah0 = *(const uint32_t*)&A0[(g    ) * AS + k0 + 2*q];
            uint32_t ah1 = *(const uint32_t*)&A0[(g + 8) * AS + k0 + 2*q];
            uint32_t ah2 = *(const uint32_t*)&A0[(g    ) * AS + k0 + 2*q + 8];
            uint32_t ah3 = *(const uint32_t*)&A0[(g + 8) * AS + k0 + 2*q + 8];
            uint32_t al0 = *(const uint32_t*)&A1[(g    ) * AS + k0 + 2*q];
            uint32_t al1 = *(const uint32_t*)&A1[(g + 8) * AS + k0 + 2*q];
            uint32_t al2 = *(const uint32_t*)&A1[(g    ) * AS + k0 + 2*q + 8];
            uint32_t al3 = *(const uint32_t*)&A1[(g + 8) * AS + k0 + 2*q + 8];
            int kg = kc * 64 + k0;
#pragma unroll
            for (int j = 0; j < 8; j++) {
                const __nv_bfloat16* w0 = W1s[0] + (8*j + g) * WS + kg + 2*q;
                const __nv_bfloat16* w1 = W1s[1] + (8*j + g) * WS + kg + 2*q;
                uint32_t bh0 = *(const uint32_t*)(w0);
                uint32_t bh1 = *(const uint32_t*)(w0 + 8);
                uint32_t bl0 = *(const uint32_t*)(w1);
                uint32_t bl1 = *(const uint32_t*)(w1 + 8);
                mma16816(acc[j], ah0, ah1, ah2, ah3, bh0, bh1);
                mma16816(acc[j], ah0, ah1, ah2, ah3, bl0, bl1);
                mma16816(acc[j], al0, al1, al2, al3, bh0, bh1);
            }
        }
    }

    // ---- gemm1 epilogue: bias + LN (quad shuffle) + ReLU -> H in smem ------
    float v0[16], v1[16];
    {
        float s0 = 0.f, q0 = 0.f, s1 = 0.f, q1 = 0.f;
#pragma unroll
        for (int j = 0; j < 8; j++) {
            int c0 = 8*j + 2*q;
            float bx = __ldg(b1 + c0), by = __ldg(b1 + c0 + 1);
            float a = acc[j][0] + bx, b = acc[j][1] + by;
            float c = acc[j][2] + bx, d = acc[j][3] + by;
            v0[2*j] = a; v0[2*j+1] = b; v1[2*j] = c; v1[2*j+1] = d;
            s0 += a + b; q0 += a*a + b*b;
            s1 += c + d; q1 += c*c + d*d;
        }
#pragma unroll
        for (int off = 1; off < 4; off <<= 1) {
            s0 += __shfl_xor_sync(0xffffffffu, s0, off);
            q0 += __shfl_xor_sync(0xffffffffu, q0, off);
            s1 += __shfl_xor_sync(0xffffffffu, s1, off);
            q1 += __shfl_xor_sync(0xffffffffu, q1, off);
        }
        float mu0 = s0 * (1.f/64.f), var0 = q0 * (1.f/64.f) - mu0*mu0;
        float mu1 = s1 * (1.f/64.f), var1 = q1 * (1.f/64.f) - mu1*mu1;
        float rs0 = rsqrtf(var0 + LN_EPS), rs1 = rsqrtf(var1 + LN_EPS);
        __syncthreads();     // all MMA reads of As done before overwrite as H
        int rl0 = wid * 16 + g, rl1 = rl0 + 8;
#pragma unroll
        for (int j = 0; j < 8; j++) {
            int c0 = 8*j + 2*q;
            float ga = __ldg(gam + c0), gb = __ldg(gam + c0 + 1);
            float ba = __ldg(bet + c0), bb = __ldg(bet + c0 + 1);
            float f0 = fmaxf((v0[2*j]   - mu0) * rs0 * ga + ba, 0.f);
            float f1 = fmaxf((v0[2*j+1] - mu0) * rs0 * gb + bb, 0.f);
            float f2 = fmaxf((v1[2*j]   - mu1) * rs1 * ga + ba, 0.f);
            float f3 = fmaxf((v1[2*j+1] - mu1) * rs1 * gb + bb, 0.f);
            uint32_t h, l;
            split2(f0, f1, h, l);
            *(uint32_t*)&As[0][rl0 * AS + c0] = h;
            *(uint32_t*)&As[1][rl0 * AS + c0] = l;
            split2(f2, f3, h, l);
            *(uint32_t*)&As[0][rl1 * AS + c0] = h;
            *(uint32_t*)&As[1][rl1 * AS + c0] = l;
        }
    }
    __syncthreads();

    // ---- gemm2: H[128,64] @ W2 -> Y first half -----------------------------
    const __nv_bfloat16* H0 = As[0] + (wid * 16) * AS;
    const __nv_bfloat16* H1 = As[1] + (wid * 16) * AS;
    const int rg0 = r0 + wid * 16 + g;
    const int rg1 = rg0 + 8;

#pragma unroll
    for (int ng = 0; ng < NG; ng++) {
        float acc2[8][4] = {};
#pragma unroll
        for (int ks = 0; ks < 4; ks++) {
            int k0 = ks * 16;
            uint32_t ah0 = *(const uint32_t*)&H0[(g    ) * AS + k0 + 2*q];
            uint32_t ah1 = *(const uint32_t*)&H0[(g + 8) * AS + k0 + 2*q];
            uint32_t ah2 = *(const uint32_t*)&H0[(g    ) * AS + k0 + 2*q + 8];
            uint32_t ah3 = *(const uint32_t*)&H0[(g + 8) * AS + k0 + 2*q + 8];
            uint32_t al0 = *(const uint32_t*)&H1[(g    ) * AS + k0 + 2*q];
            uint32_t al1 = *(const uint32_t*)&H1[(g + 8) * AS + k0 + 2*q];
            uint32_t al2 = *(const uint32_t*)&H1[(g    ) * AS + k0 + 2*q + 8];
            uint32_t al3 = *(const uint32_t*)&H1[(g + 8) * AS + k0 + 2*q + 8];
#pragma unroll
            for (int j = 0; j < 8; j++) {
                const __nv_bfloat16* w0 = W2s[0] + (ng*64 + 8*j + g) * AS + k0 + 2*q;
                const __nv_bfloat16* w1 = W2s[1] + (ng*64 + 8*j + g) * AS + k0 + 2*q;
                uint32_t bh0 = *(const uint32_t*)(w0);
                uint32_t bh1 = *(const uint32_t*)(w0 + 8);
                uint32_t bl0 = *(const uint32_t*)(w1);
                uint32_t bl1 = *(const uint32_t*)(w1 + 8);
                mma16816(acc2[j], ah0, ah1, ah2, ah3, bh0, bh1);
                mma16816(acc2[j], ah0, ah1, ah2, ah3, bl0, bl1);
                mma16816(acc2[j], al0, al1, al2, al3, bh0, bh1);
            }
        }
        if (rg0 < n) {
            uint2* orow = Y + (size_t)rg0 * C;
#pragma unroll
            for (int j = 0; j < 8; j++) {
                int c0 = 8*j + 2*q;
                float f0 = acc2[j][0] + __ldg(b2 + ng*64 + c0);
                float f1 = acc2[j][1] + __ldg(b2 + ng*64 + c0 + 1);
                uint32_t h, l; split2(f0, f1, h, l);
                orow[ng*32 + 4*j + q] = make_uint2(h, l);
            }
        }
        if (rg1 < n) {
            uint2* orow = Y + (size_t)rg1 * C;
#pragma unroll
            for (int j = 0; j < 8; j++) {
                int c0 = 8*j + 2*q;
                float f0 = acc2[j][2] + __ldg(b2 + ng*64 + c0);
                float f1 = acc2[j][3] + __ldg(b2 + ng*64 + c0 + 1);
                uint32_t h, l; split2(f0, f1, h, l);
                orow[ng*32 + 4*j + q] = make_uint2(h, l);
            }
        }
    }
}

// ---------------- CSR gather-max aggregation (interleaved) -------------------
// warp per target node; first-half entries C/2 over 32 lanes
template<int C>
__global__ __launch_bounds__(256) void agg_i(
    uint2* __restrict__ Y, const int* __restrict__ rowptr,
    const int* __restrict__ deg, const int* __restrict__ esrc, int n)
{
    int w = (blockIdx.x * blockDim.x + threadIdx.x) >> 5;
    if (w >= n) return;
    const int lane = threadIdx.x & 31;
    constexpr int EPL = C / 64;              // uint2 entries per lane
    float mx[2 * EPL];
#pragma unroll
    for (int i = 0; i < 2 * EPL; i++) mx[i] = neg_inf();
    int d = __ldg(deg + w), base = __ldg(rowptr + w);
    for (int j = 0; j < d; j++) {
        int src = __ldg(esrc + base + j);
        const uint2* row = Y + (size_t)src * C;
#pragma unroll
        for (int i = 0; i < EPL; i++) {
            uint2 v = __ldg(row + lane + i * 32);
            float2 fh = __bfloat1622float2(*(__nv_bfloat162*)&v.x);
            float2 fl = __bfloat1622float2(*(__nv_bfloat162*)&v.y);
            mx[2*i]   = fmaxf(mx[2*i],   fh.x + fl.x);
            mx[2*i+1] = fmaxf(mx[2*i+1], fh.y + fl.y);
        }
    }
    uint2* orow = Y + (size_t)w * C + C / 2;
#pragma unroll
    for (int i = 0; i < EPL; i++) {
        uint32_t h = 0, l = 0;
        if (d) split2(mx[2*i], mx[2*i+1], h, l);
        orow[lane + i * 32] = make_uint2(h, l);
    }
}

// ---------------- CSR cluster max-pool (interleaved in, fp32 out) -----------
__global__ __launch_bounds__(128) void pool_i(
    const uint2* __restrict__ Y, const int* __restrict__ cptr,
    const int* __restrict__ cdeg, const int* __restrict__ cnodes,
    float* __restrict__ out)
{
    int cl = blockIdx.x, t = threadIdx.x;
    int d = __ldg(cdeg + cl), base = __ldg(cptr + cl);
    float m0 = neg_inf(), m1 = neg_inf(), m2 = neg_inf(), m3 = neg_inf();
    for (int j = 0; j < d; j++) {
        int nd = __ldg(cnodes + base + j);
        const uint2* row = Y + (size_t)nd * 256;
        uint2 u0 = __ldg(row + t);
        uint2 u1 = __ldg(row + t + 128);
        float2 a = __bfloat1622float2(*(__nv_bfloat162*)&u0.x);
        float2 b = __bfloat1622float2(*(__nv_bfloat162*)&u0.y);
        float2 c = __bfloat1622float2(*(__nv_bfloat162*)&u1.x);
        float2 e = __bfloat1622float2(*(__nv_bfloat162*)&u1.y);
        m0 = fmaxf(m0, a.x + b.x); m1 = fmaxf(m1, a.y + b.y);
        m2 = fmaxf(m2, c.x + e.x); m3 = fmaxf(m3, c.y + e.y);
    }
    if (!d) { m0 = m1 = m2 = m3 = 0.f; }
    out[(size_t)cl * 512 + 2 * t]           = m0;
    out[(size_t)cl * 512 + 2 * t + 1]       = m1;
    out[(size_t)cl * 512 + 256 + 2 * t]     = m2;
    out[(size_t)cl * 512 + 256 + 2 * t + 1] = m3;
}

// ---------------- column L2 normalize ---------------------------------------
__global__ __launch_bounds__(512) void colsq_kernel(const float* __restrict__ out,
                                                    float* __restrict__ colsq, int nc)
{
    const int ROWS = 50;
    int c  = threadIdx.x;
    int r0 = blockIdx.x * ROWS;
    int r1 = min(r0 + ROWS, nc);
    float s = 0.f;
    for (int r = r0; r < r1; r++) {
        float f = out[(size_t)r * 512 + c];
        s += f * f;
    }
    atomicAdd(colsq + c, s);
}

__global__ void scale_kernel(float* __restrict__ out, const float* __restrict__ colsq, int nc)
{
    int gid = blockIdx.x * blockDim.x + threadIdx.x;
    if (gid >= nc * 512) return;
    int c = gid & 511;
    out[gid] = out[gid] / sqrtf(__ldg(colsq + c));
}

// ---------------- launch ----------------------------------------------------
extern "C" void kernel_launch(void* const* d_in, const int* in_sizes, int n_in,
                              void* d_out, int out_size)
{
    const float* x       = (const float*)d_in[0];
    const int*   ei      = (const int*)d_in[1];
    const int*   cluster = (const int*)d_in[2];
    const int N  = in_sizes[0] / 64;
    const int E  = in_sizes[1] / 2;
    const int NC = out_size / 512;
    float* out = (float*)d_out;

    uint2 *y0, *y1, *y2;
    __nv_bfloat16 *w1h[3], *w1l[3], *w2h[3], *w2l[3];
    float *colsq;
    int *deg, *rowptr, *cursor, *esrc, *cdeg, *cptr, *ccur, *cnodes, *bsumsN, *bsumsC;
    cudaGetSymbolAddress((void**)&y0, g_y0);
    cudaGetSymbolAddress((void**)&y1, g_y1);
    cudaGetSymbolAddress((void**)&y2, g_y2);
    cudaGetSymbolAddress((void**)&w1h[0], g_w1thi0); cudaGetSymbolAddress((void**)&w1l[0], g_w1tlo0);
    cudaGetSymbolAddress((void**)&w1h[1], g_w1thi1); cudaGetSymbolAddress((void**)&w1l[1], g_w1tlo1);
    cudaGetSymbolAddress((void**)&w1h[2], g_w1thi2); cudaGetSymbolAddress((void**)&w1l[2], g_w1tlo2);
    cudaGetSymbolAddress((void**)&w2h[0], g_w2thi0); cudaGetSymbolAddress((void**)&w2l[0], g_w2tlo0);
    cudaGetSymbolAddress((void**)&w2h[1], g_w2thi1); cudaGetSymbolAddress((void**)&w2l[1], g_w2tlo1);
    cudaGetSymbolAddress((void**)&w2h[2], g_w2thi2); cudaGetSymbolAddress((void**)&w2l[2], g_w2tlo2);
    cudaGetSymbolAddress((void**)&colsq,  g_colsq);
    cudaGetSymbolAddress((void**)&deg,    g_deg);
    cudaGetSymbolAddress((void**)&rowptr, g_rowptr);
    cudaGetSymbolAddress((void**)&cursor, g_cursor);
    cudaGetSymbolAddress((void**)&esrc,   g_esrc);
    cudaGetSymbolAddress((void**)&cdeg,   g_cdeg);
    cudaGetSymbolAddress((void**)&cptr,   g_cptr);
    cudaGetSymbolAddress((void**)&ccur,   g_ccur);
    cudaGetSymbolAddress((void**)&cnodes, g_cnodes);
    cudaGetSymbolAddress((void**)&bsumsN, g_bsumsN);
    cudaGetSymbolAddress((void**)&bsumsC, g_bsumsC);

    // dynamic smem per specialization: 2*(64*(C+8) + 128*72 + C*72)*2 bytes
    const int SM64  = 2 * (64*72  + 128*72 + 64*72 ) * 2;   //  73728
    const int SM128 = 2 * (64*136 + 128*72 + 128*72) * 2;   // 108544
    const int SM256 = 2 * (64*264 + 128*72 + 256*72) * 2;   // 178176
    cudaFuncSetAttribute((const void*)fused_mlp<64,  true >, cudaFuncAttributeMaxDynamicSharedMemorySize, SM64);
    cudaFuncSetAttribute((const void*)fused_mlp<128, false>, cudaFuncAttributeMaxDynamicSharedMemorySize, SM128);
    cudaFuncSetAttribute((const void*)fused_mlp<256, false>, cudaFuncAttributeMaxDynamicSharedMemorySize, SM256);

    const int GRID = (N + 127) / 128;
    const int nbN = (N + 511) / 512;
    const int nbC = (NC + 511) / 512;

    // ---- CSR build + zeroing (6 launches) ----
    zero_all<<<(N + 255) / 256, 256>>>(deg, cursor, cdeg, ccur, colsq, N, NC);
    hist_fused<<<(E + N + 255) / 256, 256>>>(ei, E, cluster, N, deg, cdeg);
    scan_block2<<<nbN + nbC, 512>>>(deg, rowptr, bsumsN, N, nbN, cdeg, cptr, bsumsC, NC);
    scan_sums2<<<2, 256>>>(bsumsN, nbN, bsumsC, nbC);
    scan_add2<<<nbN + nbC, 512>>>(rowptr, bsumsN, N, nbN, cptr, bsumsC, NC);
    scatter_fused<<<(E + N + 255) / 256, 256>>>(ei, E, cluster, N, rowptr, cursor, esrc,
                                                cptr, ccur, cnodes);

    // ---- weight conversion (1 launch) ----
    {
        WConv a;
        int off = 0;
        const int CINs[3] = {64, 128, 256};
        for (int i = 0; i < 3; i++) {
            int c = CINs[i];
            a.in[2*i]   = (const float*)d_in[3 + 6*i];       // W1 [c][64]
            a.hi[2*i]   = w1h[i]; a.lo[2*i] = w1l[i];
            a.K[2*i]    = c;  a.M[2*i] = 64;                 // -> [64][c]
            a.off[2*i]  = off; off += c * 64;
            a.in[2*i+1] = (const float*)d_in[3 + 6*i + 4];   // W2 [64][c]
            a.hi[2*i+1] = w2h[i]; a.lo[2*i+1] = w2l[i];
            a.K[2*i+1]  = 64; a.M[2*i+1] = c;                // -> [c][64]
            a.off[2*i+1] = off; off += 64 * c;
        }
        a.off[6] = off;
        conv_weights<<<(off + 255) / 256, 256>>>(a);
    }

    // ---- layers ----
    fused_mlp<64, true><<<GRID, 256, SM64>>>(
        x, w1h[0], w1l[0], (const float*)d_in[4], (const float*)d_in[5],
        (const float*)d_in[6], w2h[0], w2l[0], (const float*)d_in[8], y0, N);
    agg_i<64><<<(N + 7) / 8, 256>>>(y0, rowptr, deg, esrc, N);

    fused_mlp<128, false><<<GRID, 256, SM128>>>(
        y0, w1h[1], w1l[1], (const float*)d_in[10], (const float*)d_in[11],
        (const float*)d_in[12], w2h[1], w2l[1], (const float*)d_in[14], y1, N);
    agg_i<128><<<(N + 7) / 8, 256>>>(y1, rowptr, deg, esrc, N);

    fused_mlp<256, false><<<GRID, 256, SM256>>>(
        y1, w1h[2], w1l[2], (const float*)d_in[16], (const float*)d_in[17],
        (const float*)d_in[18], w2h[2], w2l[2], (const float*)d_in[20], y2, N);
    agg_i<256><<<(N + 7) / 8, 256>>>(y2, rowptr, deg, esrc, N);

    // ---- cluster max-pool + column L2 normalize ----
    pool_i<<<NC, 128>>>(y2, cptr, cdeg, cnodes, out);
    colsq_kernel<<<(NC + 49) / 50, 512>>>(out, colsq, NC);
    scale_kernel<<<(NC * 512 + 255) / 256, 256>>>(out, colsq, NC);
}

// round 8
// speedup vs baseline: 3.5451x; 1.0496x over previous
#include <cuda_runtime.h>
#include <cuda_bf16.h>
#include <cstdint>

#define LN_EPS 1e-5f

// ---------------- scratch (device globals: allocation-free) ----------------
__device__ __align__(128) float g_y0[100000 * 128];   // layer0 out [n, 128] fp32
__device__ __align__(128) float g_y1[100000 * 256];   // layer1 out [n, 256]
__device__ __align__(128) float g_y2[100000 * 512];   // layer2 out [n, 512]
__device__ __align__(128) __nv_bfloat16 g_w1thi0[64*64],  g_w1tlo0[64*64];
__device__ __align__(128) __nv_bfloat16 g_w1thi1[64*128], g_w1tlo1[64*128];
__device__ __align__(128) __nv_bfloat16 g_w1thi2[64*256], g_w1tlo2[64*256];
__device__ __align__(128) __nv_bfloat16 g_w2thi0[64*64],  g_w2tlo0[64*64];
__device__ __align__(128) __nv_bfloat16 g_w2thi1[128*64], g_w2tlo1[128*64];
__device__ __align__(128) __nv_bfloat16 g_w2thi2[256*64], g_w2tlo2[256*64];
__device__ float g_colsq[512];

// CSR scratch
__device__ int g_deg[100000];
__device__ int g_rowptr[100000];
__device__ int g_cursor[100000];
__device__ int g_esrc[800000];
__device__ int g_cdeg[10000];
__device__ int g_cptr[10000];
__device__ int g_ccur[10000];
__device__ int g_cnodes[100000];
__device__ int g_bsumsN[512];
__device__ int g_bsumsC[512];

__device__ __forceinline__ float neg_inf() { return __int_as_float(0xff800000); }

// fp32 pair -> (bf16 hi, bf16 lo) packed words
__device__ __forceinline__ void split2(float a, float b, uint32_t& hi, uint32_t& lo) {
    __nv_bfloat16 ah = __float2bfloat16_rn(a);
    __nv_bfloat16 bh = __float2bfloat16_rn(b);
    __nv_bfloat16 al = __float2bfloat16_rn(a - __bfloat162float(ah));
    __nv_bfloat16 bl = __float2bfloat16_rn(b - __bfloat162float(bh));
    __nv_bfloat162 h = __halves2bfloat162(ah, bh);
    __nv_bfloat162 l = __halves2bfloat162(al, bl);
    hi = *reinterpret_cast<uint32_t*>(&h);
    lo = *reinterpret_cast<uint32_t*>(&l);
}

__device__ __forceinline__ void mma16816(float* c, const uint32_t* a,
                                         uint32_t b0, uint32_t b1) {
    asm volatile(
        "mma.sync.aligned.m16n8k16.row.col.f32.bf16.bf16.f32 "
        "{%0,%1,%2,%3}, {%4,%5,%6,%7}, {%8,%9}, {%0,%1,%2,%3};"
        : "+f"(c[0]), "+f"(c[1]), "+f"(c[2]), "+f"(c[3])
        : "r"(a[0]), "r"(a[1]), "r"(a[2]), "r"(a[3]), "r"(b0), "r"(b1));
}

__device__ __forceinline__ uint32_t sm_off(const void* p) {
    uint32_t a;
    asm("{ .reg .u64 t; cvta.to.shared.u64 t, %1; cvt.u32.u64 %0, t; }" : "=r"(a) : "l"(p));
    return a;
}

__device__ __forceinline__ void ldsm_x4(uint32_t& r0, uint32_t& r1,
                                        uint32_t& r2, uint32_t& r3, uint32_t addr) {
    asm volatile("ldmatrix.sync.aligned.m8n8.x4.shared.b16 {%0,%1,%2,%3}, [%4];"
                 : "=r"(r0), "=r"(r1), "=r"(r2), "=r"(r3) : "r"(addr));
}

// ---------------- init: zero CSR counters + convert all weights -------------
struct WConv {
    const float* in[6];
    __nv_bfloat16* hi[6];
    __nv_bfloat16* lo[6];
    int K[6], M[6];
    int off[7];
};

__global__ void init_misc(WConv a, int* __restrict__ deg, int* __restrict__ cursor,
                          int* __restrict__ cdeg, int* __restrict__ ccur,
                          float* __restrict__ colsq, int n, int nc)
{
    int gid = blockIdx.x * blockDim.x + threadIdx.x;
    if (gid < n) { deg[gid] = 0; cursor[gid] = 0; }
    if (gid < nc) { cdeg[gid] = 0; ccur[gid] = 0; }
    if (gid < 512) colsq[gid] = 0.f;
    if (gid < a.off[6]) {
        int s = 0;
#pragma unroll
        for (int i = 1; i < 6; i++) if (gid >= a.off[i]) s = i;
        int local = gid - a.off[s];
        int M = a.M[s], K = a.K[s];
        int k = local / M, m = local - k * M;
        float v = __ldg(a.in[s] + local);
        __nv_bfloat16 h = __float2bfloat16_rn(v);
        a.hi[s][m * K + k] = h;
        a.lo[s][m * K + k] = __float2bfloat16_rn(v - __bfloat162float(h));
    }
}

// ---------------- CSR build --------------------------------------------------
__global__ void hist_fused(const int* __restrict__ ei, int E,
                           const int* __restrict__ cluster, int n,
                           int* __restrict__ deg, int* __restrict__ cdeg)
{
    int gid = blockIdx.x * blockDim.x + threadIdx.x;
    if (gid < E) {
        atomicAdd(&deg[__ldg(ei + E + gid)], 1);
    } else if (gid < E + n) {
        atomicAdd(&cdeg[__ldg(cluster + gid - E)], 1);
    }
}

__global__ __launch_bounds__(512) void scan_block2(
    const int* __restrict__ inN, int* __restrict__ outN, int* __restrict__ sumsN, int n, int nbN,
    const int* __restrict__ inC, int* __restrict__ outC, int* __restrict__ sumsC, int nc)
{
    __shared__ int s[512];
    int tid = threadIdx.x;
    const int* in;  int* out; int* sums; int len; int blk;
    if ((int)blockIdx.x < nbN) { in = inN; out = outN; sums = sumsN; len = n;  blk = blockIdx.x; }
    else                       { in = inC; out = outC; sums = sumsC; len = nc; blk = blockIdx.x - nbN; }
    int i = blk * 512 + tid;
    int v = (i < len) ? in[i] : 0;
    s[tid] = v;
    __syncthreads();
#pragma unroll
    for (int off = 1; off < 512; off <<= 1) {
        int t = (tid >= off) ? s[tid - off] : 0;
        __syncthreads();
        s[tid] += t;
        __syncthreads();
    }
    if (i < len) out[i] = s[tid] - v;
    if (tid == 511) sums[blk] = s[511];
}

// add prefix of block sums (each block re-reduces its own prefix; <=196 reads)
__global__ __launch_bounds__(512) void scan_add_fused(
    int* __restrict__ outN, const int* __restrict__ sumsN, int n, int nbN,
    int* __restrict__ outC, const int* __restrict__ sumsC, int nc)
{
    __shared__ int red[16];
    __shared__ int total;
    int tid = threadIdx.x;
    int* out; const int* sums; int len; int blk;
    if ((int)blockIdx.x < nbN) { out = outN; sums = sumsN; len = n;  blk = blockIdx.x; }
    else                       { out = outC; sums = sumsC; len = nc; blk = blockIdx.x - nbN; }
    int p = 0;
    for (int i = tid; i < blk; i += 512) p += sums[i];
#pragma unroll
    for (int off = 16; off >= 1; off >>= 1) p += __shfl_xor_sync(0xffffffffu, p, off);
    if ((tid & 31) == 0) red[tid >> 5] = p;
    __syncthreads();
    if (tid == 0) {
        int t = 0;
#pragma unroll
        for (int i = 0; i < 16; i++) t += red[i];
        total = t;
    }
    __syncthreads();
    int i = blk * 512 + tid;
    if (i < len) out[i] += total;
}

__global__ void scatter_fused(const int* __restrict__ ei, int E,
                              const int* __restrict__ cluster, int n,
                              const int* __restrict__ rowptr, int* __restrict__ cursor,
                              int* __restrict__ esrc,
                              const int* __restrict__ cptr, int* __restrict__ ccur,
                              int* __restrict__ cnodes)
{
    int gid = blockIdx.x * blockDim.x + threadIdx.x;
    if (gid < E) {
        int src = __ldg(ei + gid);
        int tgt = __ldg(ei + E + gid);
        int pos = rowptr[tgt] + atomicAdd(&cursor[tgt], 1);
        esrc[pos] = src;
    } else if (gid < E + n) {
        int i = gid - E;
        int cl = __ldg(cluster + i);
        int pos = cptr[cl] + atomicAdd(&ccur[cl], 1);
        cnodes[pos] = i;
    }
}

// ---------------- fused MLP layer: gemm1+bias+LN+ReLU+gemm2+bias ------------
// Ain [n, C] fp32; W1T [64][C] split bf16, W2T [C][64] split bf16
// Y [n, 2C] fp32: first C cols written here, rest by agg
template<int C>
__global__ __launch_bounds__(256) void fused_mlp(
    const float* __restrict__ Ain,
    const __nv_bfloat16* __restrict__ W1hi, const __nv_bfloat16* __restrict__ W1lo,
    const float* __restrict__ b1, const float* __restrict__ gam,
    const float* __restrict__ bet,
    const __nv_bfloat16* __restrict__ W2hi, const __nv_bfloat16* __restrict__ W2lo,
    const float* __restrict__ b2,
    float* __restrict__ Y, int n)
{
    constexpr int AS  = 72;
    constexpr int WS  = C + 8;
    constexpr int NKC = C / 64;
    constexpr int NG  = C / 64;
    constexpr int W1E = 64 * WS;
    constexpr int AE  = 128 * AS;
    extern __shared__ __align__(16) __nv_bfloat16 sm[];
    __nv_bfloat16* W1s0 = sm;
    __nv_bfloat16* W1s1 = sm + W1E;
    __nv_bfloat16* As0  = sm + 2 * W1E;
    __nv_bfloat16* As1  = As0 + AE;
    __nv_bfloat16* W2s0 = As1 + AE;
    __nv_bfloat16* W2s1 = W2s0 + C * AS;

    const int tid = threadIdx.x, wid = tid >> 5, lane = tid & 31;
    const int g = lane >> 2, q = lane & 3;
    const int r0b = blockIdx.x * 128;

    // load weights
    {
        constexpr int VPR = C / 8;
        for (int i = tid; i < 64 * VPR; i += 256) {
            int m = i / VPR, seg = i - m * VPR;
            *(uint4*)&W1s0[m * WS + seg * 8] = __ldg((const uint4*)(W1hi + (size_t)m * C) + seg);
            *(uint4*)&W1s1[m * WS + seg * 8] = __ldg((const uint4*)(W1lo + (size_t)m * C) + seg);
        }
        for (int i = tid; i < C * 8; i += 256) {
            int m = i >> 3, seg = i & 7;
            *(uint4*)&W2s0[m * AS + seg * 8] = __ldg((const uint4*)(W2hi + (size_t)m * 64) + seg);
            *(uint4*)&W2s1[m * AS + seg * 8] = __ldg((const uint4*)(W2lo + (size_t)m * 64) + seg);
        }
    }

    // per-thread ldmatrix address bases
    const int arow = wid * 16 + (lane & 15);
    const int acol = ((lane >> 4) & 1) * 8;
    const uint32_t a_hi = sm_off(As0 + arow * AS + acol);
    const uint32_t a_lo = sm_off(As1 + arow * AS + acol);
    const int brow = (lane & 7) + ((lane >> 4) << 3);       // 0..15
    const int bk8  = ((lane >> 3) & 1) * 8;
    const uint32_t w1h_b = sm_off(W1s0 + brow * WS + bk8);
    const uint32_t w1l_b = sm_off(W1s1 + brow * WS + bk8);
    const uint32_t w2h_b = sm_off(W2s0 + brow * AS + bk8);
    const uint32_t w2l_b = sm_off(W2s1 + brow * AS + bk8);

    float acc[8][4] = {};

    for (int kc = 0; kc < NKC; kc++) {
        __syncthreads();
        for (int i = tid; i < 128 * 32; i += 256) {
            int m = i >> 5, e = i & 31;
            int r = r0b + m;
            uint32_t h = 0, l = 0;
            if (r < n) {
                float2 v = __ldg((const float2*)Ain + (size_t)r * (C / 2) + kc * 32 + e);
                split2(v.x, v.y, h, l);
            }
            *(uint32_t*)&As0[m * AS + 2 * e] = h;
            *(uint32_t*)&As1[m * AS + 2 * e] = l;
        }
        __syncthreads();

#pragma unroll
        for (int ks = 0; ks < 4; ks++) {
            const int k0 = ks * 16;
            uint32_t ah[4], al[4];
            ldsm_x4(ah[0], ah[1], ah[2], ah[3], a_hi + k0 * 2);
            ldsm_x4(al[0], al[1], al[2], al[3], a_lo + k0 * 2);
            const int kg = kc * 64 + k0;
#pragma unroll
            for (int jj = 0; jj < 8; jj += 2) {
                uint32_t p0, p1, p2, p3, l0, l1, l2, l3;
                ldsm_x4(p0, p1, p2, p3, w1h_b + (8 * jj * WS + kg) * 2);
                ldsm_x4(l0, l1, l2, l3, w1l_b + (8 * jj * WS + kg) * 2);
                mma16816(acc[jj],     ah, p0, p1);
                mma16816(acc[jj],     ah, l0, l1);
                mma16816(acc[jj],     al, p0, p1);
                mma16816(acc[jj + 1], ah, p2, p3);
                mma16816(acc[jj + 1], ah, l2, l3);
                mma16816(acc[jj + 1], al, p2, p3);
            }
        }
    }

    // ---- gemm1 epilogue: bias + LN (quad shuffle) + ReLU -> H in As --------
    {
        float v0[16], v1[16];
        float s0 = 0.f, q0 = 0.f, s1 = 0.f, q1 = 0.f;
#pragma unroll
        for (int j = 0; j < 8; j++) {
            int c0 = 8*j + 2*q;
            float bx = __ldg(b1 + c0), by = __ldg(b1 + c0 + 1);
            float a = acc[j][0] + bx, b = acc[j][1] + by;
            float c = acc[j][2] + bx, d = acc[j][3] + by;
            v0[2*j] = a; v0[2*j+1] = b; v1[2*j] = c; v1[2*j+1] = d;
            s0 += a + b; q0 += a*a + b*b;
            s1 += c + d; q1 += c*c + d*d;
        }
#pragma unroll
        for (int off = 1; off < 4; off <<= 1) {
            s0 += __shfl_xor_sync(0xffffffffu, s0, off);
            q0 += __shfl_xor_sync(0xffffffffu, q0, off);
            s1 += __shfl_xor_sync(0xffffffffu, s1, off);
            q1 += __shfl_xor_sync(0xffffffffu, q1, off);
        }
        float mu0 = s0 * (1.f/64.f), var0 = q0 * (1.f/64.f) - mu0*mu0;
        float mu1 = s1 * (1.f/64.f), var1 = q1 * (1.f/64.f) - mu1*mu1;
        float rs0 = rsqrtf(var0 + LN_EPS), rs1 = rsqrtf(var1 + LN_EPS);
        __syncthreads();
        int rl0 = wid * 16 + g, rl1 = rl0 + 8;
#pragma unroll
        for (int j = 0; j < 8; j++) {
            int c0 = 8*j + 2*q;
            float ga = __ldg(gam + c0), gb = __ldg(gam + c0 + 1);
            float ba = __ldg(bet + c0), bb = __ldg(bet + c0 + 1);
            float f0 = fmaxf((v0[2*j]   - mu0) * rs0 * ga + ba, 0.f);
            float f1 = fmaxf((v0[2*j+1] - mu0) * rs0 * gb + bb, 0.f);
            float f2 = fmaxf((v1[2*j]   - mu1) * rs1 * ga + ba, 0.f);
            float f3 = fmaxf((v1[2*j+1] - mu1) * rs1 * gb + bb, 0.f);
            uint32_t h, l;
            split2(f0, f1, h, l);
            *(uint32_t*)&As0[rl0 * AS + c0] = h;
            *(uint32_t*)&As1[rl0 * AS + c0] = l;
            split2(f2, f3, h, l);
            *(uint32_t*)&As0[rl1 * AS + c0] = h;
            *(uint32_t*)&As1[rl1 * AS + c0] = l;
        }
    }
    __syncthreads();

    // ---- gemm2: H[128,64] @ W2 -> Y[:, 0:C] --------------------------------
    const int rg0 = r0b + wid * 16 + g;
    const int rg1 = rg0 + 8;

#pragma unroll
    for (int ng = 0; ng < NG; ng++) {
        float acc2[8][4] = {};
#pragma unroll
        for (int ks = 0; ks < 4; ks++) {
            const int k0 = ks * 16;
            uint32_t ah[4], al[4];
            ldsm_x4(ah[0], ah[1], ah[2], ah[3], a_hi + k0 * 2);
            ldsm_x4(al[0], al[1], al[2], al[3], a_lo + k0 * 2);
#pragma unroll
            for (int jj = 0; jj < 8; jj += 2) {
                uint32_t p0, p1, p2, p3, l0, l1, l2, l3;
                ldsm_x4(p0, p1, p2, p3, w2h_b + ((ng * 64 + 8 * jj) * AS + k0) * 2);
                ldsm_x4(l0, l1, l2, l3, w2l_b + ((ng * 64 + 8 * jj) * AS + k0) * 2);
                mma16816(acc2[jj],     ah, p0, p1);
                mma16816(acc2[jj],     ah, l0, l1);
                mma16816(acc2[jj],     al, p0, p1);
                mma16816(acc2[jj + 1], ah, p2, p3);
                mma16816(acc2[jj + 1], ah, l2, l3);
                mma16816(acc2[jj + 1], al, p2, p3);
            }
        }
        if (rg0 < n) {
            float2* orow = (float2*)(Y + (size_t)rg0 * (2 * C)) + ng * 32;
#pragma unroll
            for (int j = 0; j < 8; j++) {
                int c0 = 8*j + 2*q;
                orow[4*j + q] = make_float2(acc2[j][0] + __ldg(b2 + ng*64 + c0),
                                            acc2[j][1] + __ldg(b2 + ng*64 + c0 + 1));
            }
        }
        if (rg1 < n) {
            float2* orow = (float2*)(Y + (size_t)rg1 * (2 * C)) + ng * 32;
#pragma unroll
            for (int j = 0; j < 8; j++) {
                int c0 = 8*j + 2*q;
                orow[4*j + q] = make_float2(acc2[j][2] + __ldg(b2 + ng*64 + c0),
                                            acc2[j][3] + __ldg(b2 + ng*64 + c0 + 1));
            }
        }
    }
}

// ---------------- CSR gather-max aggregation (fp32, unrolled x2) ------------
template<int C>
__global__ __launch_bounds__(256) void agg_f(
    float* __restrict__ Y, const int* __restrict__ rowptr,
    const int* __restrict__ deg, const int* __restrict__ esrc, int n)
{
    int w = (blockIdx.x * blockDim.x + threadIdx.x) >> 5;
    if (w >= n) return;
    const int lane = threadIdx.x & 31;
    constexpr int EPL = C / 64;              // float2 entries per lane
    float2 mx[EPL];
#pragma unroll
    for (int i = 0; i < EPL; i++) mx[i] = make_float2(neg_inf(), neg_inf());
    int d = __ldg(deg + w), base = __ldg(rowptr + w);
    int j = 0;
    for (; j + 1 < d; j += 2) {
        int s0 = __ldg(esrc + base + j);
        int s1 = __ldg(esrc + base + j + 1);
        const float2* r0 = (const float2*)(Y + (size_t)s0 * (2 * C));
        const float2* r1 = (const float2*)(Y + (size_t)s1 * (2 * C));
#pragma unroll
        for (int i = 0; i < EPL; i++) {
            float2 v0 = __ldg(r0 + lane + i * 32);
            float2 v1 = __ldg(r1 + lane + i * 32);
            mx[i].x = fmaxf(mx[i].x, fmaxf(v0.x, v1.x));
            mx[i].y = fmaxf(mx[i].y, fmaxf(v0.y, v1.y));
        }
    }
    if (j < d) {
        int s0 = __ldg(esrc + base + j);
        const float2* r0 = (const float2*)(Y + (size_t)s0 * (2 * C));
#pragma unroll
        for (int i = 0; i < EPL; i++) {
            float2 v0 = __ldg(r0 + lane + i * 32);
            mx[i].x = fmaxf(mx[i].x, v0.x);
            mx[i].y = fmaxf(mx[i].y, v0.y);
        }
    }
    float2* orow = (float2*)(Y + (size_t)w * (2 * C) + C);
#pragma unroll
    for (int i = 0; i < EPL; i++)
        orow[lane + i * 32] = d ? mx[i] : make_float2(0.f, 0.f);
}

// ---------------- CSR cluster max-pool (fp32, unrolled x2) ------------------
__global__ __launch_bounds__(128) void pool_f(
    const float* __restrict__ Y, const int* __restrict__ cptr,
    const int* __restrict__ cdeg, const int* __restrict__ cnodes,
    float* __restrict__ out)
{
    int cl = blockIdx.x, t = threadIdx.x;
    int d = __ldg(cdeg + cl), base = __ldg(cptr + cl);
    float2 m0 = make_float2(neg_inf(), neg_inf());
    float2 m1 = m0;
    int j = 0;
    for (; j + 1 < d; j += 2) {
        int n0 = __ldg(cnodes + base + j);
        int n1 = __ldg(cnodes + base + j + 1);
        const float2* ra = (const float2*)(Y + (size_t)n0 * 512);
        const float2* rb = (const float2*)(Y + (size_t)n1 * 512);
        float2 a0 = __ldg(ra + t), a1 = __ldg(ra + t + 128);
        float2 b0 = __ldg(rb + t), b1 = __ldg(rb + t + 128);
        m0.x = fmaxf(m0.x, fmaxf(a0.x, b0.x)); m0.y = fmaxf(m0.y, fmaxf(a0.y, b0.y));
        m1.x = fmaxf(m1.x, fmaxf(a1.x, b1.x)); m1.y = fmaxf(m1.y, fmaxf(a1.y, b1.y));
    }
    if (j < d) {
        int n0 = __ldg(cnodes + base + j);
        const float2* ra = (const float2*)(Y + (size_t)n0 * 512);
        float2 a0 = __ldg(ra + t), a1 = __ldg(ra + t + 128);
        m0.x = fmaxf(m0.x, a0.x); m0.y = fmaxf(m0.y, a0.y);
        m1.x = fmaxf(m1.x, a1.x); m1.y = fmaxf(m1.y, a1.y);
    }
    if (!d) { m0 = make_float2(0.f, 0.f); m1 = m0; }
    float2* orow = (float2*)(out + (size_t)cl * 512);
    orow[t] = m0;
    orow[t + 128] = m1;
}

// ---------------- column L2 normalize ---------------------------------------
__global__ __launch_bounds__(512) void colsq_kernel(const float* __restrict__ out,
                                                    float* __restrict__ colsq, int nc)
{
    const int ROWS = 50;
    int c  = threadIdx.x;
    int r0 = blockIdx.x * ROWS;
    int r1 = min(r0 + ROWS, nc);
    float s = 0.f;
    for (int r = r0; r < r1; r++) {
        float f = out[(size_t)r * 512 + c];
        s += f * f;
    }
    atomicAdd(colsq + c, s);
}

__global__ void scale_kernel(float* __restrict__ out, const float* __restrict__ colsq, int nc)
{
    int gid = blockIdx.x * blockDim.x + threadIdx.x;
    if (gid >= nc * 512) return;
    int c = gid & 511;
    out[gid] = out[gid] / sqrtf(__ldg(colsq + c));
}

// ---------------- launch ----------------------------------------------------
extern "C" void kernel_launch(void* const* d_in, const int* in_sizes, int n_in,
                              void* d_out, int out_size)
{
    const float* x       = (const float*)d_in[0];
    const int*   ei      = (const int*)d_in[1];
    const int*   cluster = (const int*)d_in[2];
    const int N  = in_sizes[0] / 64;
    const int E  = in_sizes[1] / 2;
    const int NC = out_size / 512;
    float* out = (float*)d_out;

    float *y0, *y1, *y2, *colsq;
    __nv_bfloat16 *w1h[3], *w1l[3], *w2h[3], *w2l[3];
    int *deg, *rowptr, *cursor, *esrc, *cdeg, *cptr, *ccur, *cnodes, *bsumsN, *bsumsC;
    cudaGetSymbolAddress((void**)&y0, g_y0);
    cudaGetSymbolAddress((void**)&y1, g_y1);
    cudaGetSymbolAddress((void**)&y2, g_y2);
    cudaGetSymbolAddress((void**)&w1h[0], g_w1thi0); cudaGetSymbolAddress((void**)&w1l[0], g_w1tlo0);
    cudaGetSymbolAddress((void**)&w1h[1], g_w1thi1); cudaGetSymbolAddress((void**)&w1l[1], g_w1tlo1);
    cudaGetSymbolAddress((void**)&w1h[2], g_w1thi2); cudaGetSymbolAddress((void**)&w1l[2], g_w1tlo2);
    cudaGetSymbolAddress((void**)&w2h[0], g_w2thi0); cudaGetSymbolAddress((void**)&w2l[0], g_w2tlo0);
    cudaGetSymbolAddress((void**)&w2h[1], g_w2thi1); cudaGetSymbolAddress((void**)&w2l[1], g_w2tlo1);
    cudaGetSymbolAddress((void**)&w2h[2], g_w2thi2); cudaGetSymbolAddress((void**)&w2l[2], g_w2tlo2);
    cudaGetSymbolAddress((void**)&colsq,  g_colsq);
    cudaGetSymbolAddress((void**)&deg,    g_deg);
    cudaGetSymbolAddress((void**)&rowptr, g_rowptr);
    cudaGetSymbolAddress((void**)&cursor, g_cursor);
    cudaGetSymbolAddress((void**)&esrc,   g_esrc);
    cudaGetSymbolAddress((void**)&cdeg,   g_cdeg);
    cudaGetSymbolAddress((void**)&cptr,   g_cptr);
    cudaGetSymbolAddress((void**)&ccur,   g_ccur);
    cudaGetSymbolAddress((void**)&cnodes, g_cnodes);
    cudaGetSymbolAddress((void**)&bsumsN, g_bsumsN);
    cudaGetSymbolAddress((void**)&bsumsC, g_bsumsC);

    const int SM64  = 2 * (64*72  + 128*72 + 64*72 ) * 2;   //  73728
    const int SM128 = 2 * (64*136 + 128*72 + 128*72) * 2;   // 108544
    const int SM256 = 2 * (64*264 + 128*72 + 256*72) * 2;   // 178176
    cudaFuncSetAttribute((const void*)fused_mlp<64>,  cudaFuncAttributeMaxDynamicSharedMemorySize, SM64);
    cudaFuncSetAttribute((const void*)fused_mlp<128>, cudaFuncAttributeMaxDynamicSharedMemorySize, SM128);
    cudaFuncSetAttribute((const void*)fused_mlp<256>, cudaFuncAttributeMaxDynamicSharedMemorySize, SM256);

    const int GRID = (N + 127) / 128;
    const int nbN = (N + 511) / 512;
    const int nbC = (NC + 511) / 512;

    // ---- init: zero counters + weight conversion (1 launch) ----
    {
        WConv a;
        int off = 0;
        const int CINs[3] = {64, 128, 256};
        for (int i = 0; i < 3; i++) {
            int c = CINs[i];
            a.in[2*i]   = (const float*)d_in[3 + 6*i];       // W1 [c][64] -> [64][c]
            a.hi[2*i]   = w1h[i]; a.lo[2*i] = w1l[i];
            a.K[2*i]    = c;  a.M[2*i] = 64;
            a.off[2*i]  = off; off += c * 64;
            a.in[2*i+1] = (const float*)d_in[3 + 6*i + 4];   // W2 [64][c] -> [c][64]
            a.hi[2*i+1] = w2h[i]; a.lo[2*i+1] = w2l[i];
            a.K[2*i+1]  = 64; a.M[2*i+1] = c;
            a.off[2*i+1] = off; off += 64 * c;
        }
        a.off[6] = off;
        int span = N > off ? N : off;
        init_misc<<<(span + 255) / 256, 256>>>(a, deg, cursor, cdeg, ccur, colsq, N, NC);
    }

    // ---- CSR build (4 launches) ----
    hist_fused<<<(E + N + 255) / 256, 256>>>(ei, E, cluster, N, deg, cdeg);
    scan_block2<<<nbN + nbC, 512>>>(deg, rowptr, bsumsN, N, nbN, cdeg, cptr, bsumsC, NC);
    scan_add_fused<<<nbN + nbC, 512>>>(rowptr, bsumsN, N, nbN, cptr, bsumsC, NC);
    scatter_fused<<<(E + N + 255) / 256, 256>>>(ei, E, cluster, N, rowptr, cursor, esrc,
                                                cptr, ccur, cnodes);

    // ---- layers ----
    fused_mlp<64><<<GRID, 256, SM64>>>(
        x, w1h[0], w1l[0], (const float*)d_in[4], (const float*)d_in[5],
        (const float*)d_in[6], w2h[0], w2l[0], (const float*)d_in[8], y0, N);
    agg_f<64><<<(N + 7) / 8, 256>>>(y0, rowptr, deg, esrc, N);

    fused_mlp<128><<<GRID, 256, SM128>>>(
        y0, w1h[1], w1l[1], (const float*)d_in[10], (const float*)d_in[11],
        (const float*)d_in[12], w2h[1], w2l[1], (const float*)d_in[14], y1, N);
    agg_f<128><<<(N + 7) / 8, 256>>>(y1, rowptr, deg, esrc, N);

    fused_mlp<256><<<GRID, 256, SM256>>>(
        y1, w1h[2], w1l[2], (const float*)d_in[16], (const float*)d_in[17],
        (const float*)d_in[18], w2h[2], w2l[2], (const float*)d_in[20], y2, N);
    agg_f<256><<<(N + 7) / 8, 256>>>(y2, rowptr, deg, esrc, N);

    // ---- cluster max-pool + column L2 normalize ----
    pool_f<<<NC, 128>>>(y2, cptr, cdeg, cnodes, out);
    colsq_kernel<<<(NC + 49) / 50, 512>>>(out, colsq, NC);
    scale_kernel<<<(NC * 512 + 255) / 256, 256>>>(out, colsq, NC);
}